// round 11
// baseline (speedup 1.0000x reference)
#include <cuda_runtime.h>
#include <cuda_bf16.h>
#include <cstdint>

// ---------------- problem constants ----------------
#define NN 100000
#define EE 1600000

// ---------------- scratch (device globals) ----------------
__device__ float  g_h0[(size_t)NN * 128];
__device__ float  g_sums[(size_t)NN * 128];
__device__ float  g_cnt[NN];
__device__ float  g_p1[(size_t)NN * 256];
__device__ float  g_p2[(size_t)NN * 1024];
__device__ float  g_p3[(size_t)NN * 256];
__device__ float  g_cs[1536];      // stats slices: L1 @0(256), L2 @256(1024), L3 @1280(256)
__device__ float  g_cq[1536];
__device__ float  g_scale[1024];
__device__ float  g_shift[1024];
__device__ int    g_nz;            // nonzero high words -> edges are int32
// packed split weights: [N][K/32][64] halves, chunk = [hi(32) | lo(32)]
__device__ __nv_bfloat16 g_b1[128 * 64 * 2];
__device__ __nv_bfloat16 g_b2[128 * 256 * 2];
__device__ __nv_bfloat16 g_b3[256 * 128 * 2];
__device__ __nv_bfloat16 g_b4[1024 * 256 * 2];
__device__ __nv_bfloat16 g_b5[256 * 1024 * 2];

// ---------------- helpers ----------------
__device__ __forceinline__ uint32_t smem_u32(const void* p) {
    uint32_t a;
    asm("{ .reg .u64 t; cvta.to.shared.u64 t, %1; cvt.u32.u64 %0, t; }" : "=r"(a) : "l"(p));
    return a;
}
#define LDSM4(R, addr) \
    asm volatile("ldmatrix.sync.aligned.m8n8.x4.shared.b16 {%0,%1,%2,%3}, [%4];" \
        : "=r"((R)[0]), "=r"((R)[1]), "=r"((R)[2]), "=r"((R)[3]) : "r"(addr))

__device__ __forceinline__ void mma_bf16(float* c, const uint32_t* a, const uint32_t* b) {
    asm volatile("mma.sync.aligned.m16n8k16.row.col.f32.bf16.bf16.f32 "
        "{%0,%1,%2,%3}, {%4,%5,%6,%7}, {%8,%9}, {%0,%1,%2,%3};"
        : "+f"(c[0]), "+f"(c[1]), "+f"(c[2]), "+f"(c[3])
        : "r"(a[0]), "r"(a[1]), "r"(a[2]), "r"(a[3]), "r"(b[0]), "r"(b[1]));
}
#define CP_A16(dst, src) \
    asm volatile("cp.async.ca.shared.global [%0], [%1], 16;" :: "r"(dst), "l"(src))
#define CP_COMMIT()  asm volatile("cp.async.commit_group;")
#define CP_WAIT0()   asm volatile("cp.async.wait_group 0;")
#define CP_WAIT1()   asm volatile("cp.async.wait_group 1;")

__device__ __forceinline__ void split_bf(float v, uint16_t& h, uint16_t& l) {
    __nv_bfloat16 hb = __float2bfloat16(v);
    __nv_bfloat16 lb = __float2bfloat16(v - __bfloat162float(hb));
    h = __bfloat16_as_ushort(hb);
    l = __bfloat16_as_ushort(lb);
}

// ---------------- merged prep kernels ----------------
// zero_all: sums (NN*128), cnt (NN), cs/cq (2x1536) + edge dtype detect.
// nz must be pre-zeroed (cudaMemsetAsync) before this kernel.
__global__ void zero_all(float* sums, float* cnt, float* cs, float* cq,
                         const unsigned int* ew, int* nz) {
    int i = (blockIdx.x * blockDim.x + threadIdx.x) * 4;
    const int n_sums = NN * 128;
    if (i < n_sums) {
        *(float4*)(sums + i) = make_float4(0.f, 0.f, 0.f, 0.f);
    } else {
        int j = i - n_sums;
        if (j < NN) {
            for (int q = 0; q < 4 && j + q < NN; q++) cnt[j + q] = 0.f;
        } else if (j < NN + 1536) {
            int s = j - NN;
            *(float4*)(cs + s) = make_float4(0.f, 0.f, 0.f, 0.f);
            *(float4*)(cq + s) = make_float4(0.f, 0.f, 0.f, 0.f);
        } else {
            int d = j - NN - 1536;      // detect range: d in [0, 16384), 4 checks each
            if (d < 16384) {
                unsigned int bad = 0;
                for (int q = 0; q < 4; q++) bad |= ew[2 * (d + q) + 1];
                unsigned int any = __ballot_sync(__activemask(), bad != 0u);
                if (any && (threadIdx.x & 31) == (__ffs(any) - 1)) atomicOr(nz, 1);
            }
        }
    }
}
__global__ void tsplit_all(const float* __restrict__ w1, const float* __restrict__ wl,
                           const float* __restrict__ wr, const float* __restrict__ hw1,
                           const float* __restrict__ hw2, const float* __restrict__ hw3,
                           __nv_bfloat16* b1, __nv_bfloat16* b2, __nv_bfloat16* b3,
                           __nv_bfloat16* b4, __nv_bfloat16* b5) {
    int idx = blockIdx.x * blockDim.x + threadIdx.x;
    const float* W; __nv_bfloat16* bp; int K, N; int local;
    if (idx < 8192)        { local = idx;          W = w1;  bp = b1; K = 64;   N = 128; }
    else if (idx < 40960)  { local = idx - 8192;   W = nullptr; bp = b2; K = 256; N = 128; }
    else if (idx < 73728)  { local = idx - 40960;  W = hw1; bp = b3; K = 128;  N = 256; }
    else if (idx < 335872) { local = idx - 73728;  W = hw2; bp = b4; K = 256;  N = 1024; }
    else if (idx < 598016) { local = idx - 335872; W = hw3; bp = b5; K = 1024; N = 256; }
    else return;
    int n = local / K, k = local % K;
    float v;
    if (W) v = W[(size_t)k * N + n];
    else   v = (k < 128) ? wl[k * 128 + n] : wr[(k - 128) * 128 + n];
    uint16_t h, l;
    split_bf(v, h, l);
    size_t base = ((size_t)n * (K >> 5) + (k >> 5)) * 64 + (k & 31);
    bp[base] = __ushort_as_bfloat16(h);
    bp[base + 32] = __ushort_as_bfloat16(l);
}

// ---------------- edge scatter (8 edges per warp) ----------------
__global__ void edge_kernel(const void* __restrict__ ei, const float* __restrict__ h0,
                            float* __restrict__ sums, float* __restrict__ cnt,
                            const int* __restrict__ nz) {
    int warp0 = ((blockIdx.x * blockDim.x + threadIdx.x) >> 5) * 8;
    int lane = threadIdx.x & 31;
    const int is64 = (*nz == 0);
#pragma unroll
    for (int e = warp0; e < warp0 + 8; e++) {
        long long src, dst;
        if (is64) {
            const long long* p = (const long long*)ei;
            src = p[e]; dst = p[EE + e];
        } else {
            const int* p = (const int*)ei;
            src = p[e]; dst = p[EE + e];
        }
        float4 v = *(const float4*)(h0 + src * 128 + lane * 4);
        float* d = sums + dst * 128 + lane * 4;
        asm volatile("red.global.add.v4.f32 [%0], {%1, %2, %3, %4};"
                     :: "l"(d), "f"(v.x), "f"(v.y), "f"(v.z), "f"(v.w) : "memory");
        if (lane == 0) atomicAdd(cnt + dst, 1.0f);
    }
}

__global__ void fin_bn(const float* __restrict__ cs, const float* __restrict__ cq,
                       const float* __restrict__ gm, const float* __restrict__ bt,
                       float* __restrict__ sc, float* __restrict__ sh, int ncols) {
    int c = blockIdx.x * blockDim.x + threadIdx.x;
    if (c < ncols) {
        double mean = (double)cs[c] * (1.0 / (double)NN);
        double var  = (double)cq[c] * (1.0 / (double)NN) - mean * mean;
        if (var < 0.0) var = 0.0;
        float rstd = (float)(1.0 / sqrt(var + 1e-5));
        float s = gm[c] * rstd;
        sc[c] = s;
        sh[c] = bt[c] - (float)mean * s;
    }
}

// ---------------- pipelined mma.sync bf16x3 GEMM (BK=64, 512 thr, NSUB) -----
// CTA processes NSUB M-subtiles of 128 rows, pipeline runs across subtiles.
// MODE 0: plain | MODE 1: relu(a*sc+sh) | MODE 2: k<128: A(sums)/cnt; else aux
#define DSM_BYTES 131072
#define GTH 512
#define NSUB 4

template<int MODE, int RELU, int STATS>
__global__ void __launch_bounds__(GTH, 1)
mgemm(const float* __restrict__ A, const __nv_bfloat16* __restrict__ Bpk,
      const float* __restrict__ bias, float* __restrict__ C,
      int M, int K, int N,
      const float* __restrict__ sc, const float* __restrict__ sh,
      const float* __restrict__ aux, const float* __restrict__ cnt,
      float* __restrict__ gs, float* __restrict__ gq) {
    extern __shared__ __align__(16) char dsm[];
    __shared__ float ssum[256];
    char* sAc = dsm;
    const uint32_t sA_b = smem_u32(dsm);
    const uint32_t sB_b = sA_b + 65536;

    const int tid = threadIdx.x, lane = tid & 31, wid = tid >> 5;
    const int wm = (wid & 3) * 32, wn = (wid >> 2) * 32;
    const int n0 = blockIdx.x * 128;
    const int nch = K >> 6;               // power of 2: 1,2,4,16
    const int lg = 31 - __clz(nch);
    const int kc32 = K >> 5;
    const int T = nch << 2;               // NSUB * nch

    float acc[2][4][4];
#pragma unroll
    for (int i = 0; i < 2; i++)
#pragma unroll
        for (int j = 0; j < 4; j++)
#pragma unroll
            for (int q = 0; q < 4; q++) acc[i][j][q] = 0.f;

    auto m0_of = [&](int t) { return (blockIdx.y * NSUB + (t >> lg)) * 128; };

    auto issueB = [&](int t) {
        const int buf = t & 1;
        const int c = t & (nch - 1);
        const uint32_t bb = sB_b + buf * 32768;
#pragma unroll
        for (int l = 0; l < 4; l++) {
            int pos = tid + l * GTH;
            int row = pos >> 4, q = pos & 15;
            const char* srcB = (const char*)(Bpk + ((size_t)(n0 + row) * kc32 + 2 * c) * 64) + q * 16;
            uint32_t dst = bb + row * 256 + (uint32_t)((q >> 3) * 128)
                         + (((uint32_t)((q & 7) * 16)) ^ (uint32_t)((row & 7) * 16));
            CP_A16(dst, srcB);
        }
        CP_COMMIT();
    };

    auto load_A = [&](int t, float4* rv) {
        const int k0 = (t & (nch - 1)) << 6;
        const int m0 = m0_of(t);
#pragma unroll
        for (int l = 0; l < 4; l++) {
            int pos = tid + l * GTH;
            int row = pos >> 4, q = pos & 15;
            int grow = m0 + row;
            float4 v = make_float4(0.f, 0.f, 0.f, 0.f);
            if (grow < M) {
                if (MODE == 2) {
                    if (k0 < 128) v = *(const float4*)(A + (size_t)grow * 128 + k0 + q * 4);
                    else          v = *(const float4*)(aux + (size_t)grow * 128 + (k0 - 128) + q * 4);
                } else {
                    v = *(const float4*)(A + (size_t)grow * K + k0 + q * 4);
                }
            }
            rv[l] = v;
        }
    };
    // (row, q) quad covers k = q*4..q*4+3 -> group (q>>3), in-group byte (q&7)*8
    auto split_store = [&](int t, float4* rv) {
        const int buf = t & 1;
        const int k0 = (t & (nch - 1)) << 6;
        const int m0 = m0_of(t);
        char* sAd = sAc + buf * 32768;
#pragma unroll
        for (int l = 0; l < 4; l++) {
            int pos = tid + l * GTH;
            int row = pos >> 4, q = pos & 15;
            int grow = m0 + row;
            float4 v = rv[l];
            if (MODE == 1) {
                float4 s4 = *(const float4*)(sc + k0 + q * 4);
                float4 h4 = *(const float4*)(sh + k0 + q * 4);
                v.x = fmaxf(fmaf(v.x, s4.x, h4.x), 0.f);
                v.y = fmaxf(fmaf(v.y, s4.y, h4.y), 0.f);
                v.z = fmaxf(fmaf(v.z, s4.z, h4.z), 0.f);
                v.w = fmaxf(fmaf(v.w, s4.w, h4.w), 0.f);
            }
            if (MODE == 2 && k0 < 128) {
                float cv = (grow < M) ? cnt[grow] : 1.f;
                float ic = 1.f / fmaxf(cv, 1.f);
                v.x *= ic; v.y *= ic; v.z *= ic; v.w *= ic;
            }
            uint16_t hx, hy, hz, hw_, lx, ly, lz, lw;
            split_bf(v.x, hx, lx); split_bf(v.y, hy, ly);
            split_bf(v.z, hz, lz); split_bf(v.w, hw_, lw);
            uint2 hi2 = make_uint2((uint32_t)hx | ((uint32_t)hy << 16),
                                   (uint32_t)hz | ((uint32_t)hw_ << 16));
            uint2 lo2 = make_uint2((uint32_t)lx | ((uint32_t)ly << 16),
                                   (uint32_t)lz | ((uint32_t)lw << 16));
            uint32_t xr = (uint32_t)((row & 7) * 16);
            uint32_t base = (uint32_t)(row * 256 + (q >> 3) * 128);
            uint32_t qq = (uint32_t)((q & 7) * 8);
            *(uint2*)(sAd + base + (qq ^ xr)) = hi2;
            *(uint2*)(sAd + base + ((64 + qq) ^ xr)) = lo2;
        }
    };

    // ---- prologue ----
    issueB(0);
    if (T > 1) issueB(1);
    {
        float4 rv0[4];
        load_A(0, rv0);
        split_store(0, rv0);
    }
    if (T > 1) CP_WAIT1(); else CP_WAIT0();
    __syncthreads();

    // ---- mainloop across NSUB subtiles, one barrier per chunk ----
    for (int t = 0; t < T; t++) {
        const int buf = t & 1;
        float4 rv[4];
        if (t + 1 < T) load_A(t + 1, rv);
        const uint32_t ab = sA_b + buf * 32768;
        const uint32_t bb = sB_b + buf * 32768;
#pragma unroll
        for (int ks = 0; ks < 4; ks++) {
            const uint32_t gb = (uint32_t)((ks >> 1) * 128);
            const uint32_t kb = (uint32_t)((ks & 1) * 32);
            uint32_t afh[2][4], afl[2][4];
#pragma unroll
            for (int mt = 0; mt < 2; mt++) {
                int row = wm + mt * 16 + (lane & 15);
                uint32_t cb = kb + (uint32_t)((lane >> 4) * 16);
                uint32_t x = (uint32_t)((row & 7) * 16);
                uint32_t rb = ab + row * 256 + gb;
                LDSM4(afh[mt], rb + (cb ^ x));
                LDSM4(afl[mt], rb + ((cb + 64) ^ x));
            }
            uint32_t bfh[2][4], bfl[2][4];
#pragma unroll
            for (int np = 0; np < 2; np++) {
                int row = wn + np * 16 + (lane & 7) + ((lane >> 4) & 1) * 8;
                uint32_t cb = kb + (uint32_t)(((lane >> 3) & 1) * 16);
                uint32_t x = (uint32_t)((row & 7) * 16);
                uint32_t rb = bb + row * 256 + gb;
                LDSM4(bfh[np], rb + (cb ^ x));
                LDSM4(bfl[np], rb + ((cb + 64) ^ x));
            }
#pragma unroll
            for (int mt = 0; mt < 2; mt++)
#pragma unroll
                for (int np = 0; np < 2; np++)
#pragma unroll
                    for (int sub = 0; sub < 2; sub++) {
                        int nt = np * 2 + sub;
                        mma_bf16(acc[mt][nt], afh[mt], &bfh[np][sub * 2]);
                        mma_bf16(acc[mt][nt], afl[mt], &bfh[np][sub * 2]);
                        mma_bf16(acc[mt][nt], afh[mt], &bfl[np][sub * 2]);
                    }
        }
        if (t + 1 < T) {
            split_store(t + 1, rv);
            CP_WAIT0();
        }
        __syncthreads();
        if (t + 2 < T) issueB(t + 2);

        // ---- subtile epilogue ----
        if ((t & (nch - 1)) == nch - 1) {
            const int m0 = m0_of(t);
            if (STATS) {
                if (tid < 256) ssum[tid] = 0.f;
                __syncthreads();
            }
#pragma unroll
            for (int mt = 0; mt < 2; mt++) {
                int row = m0 + wm + mt * 16 + (lane >> 2);
#pragma unroll
                for (int nt = 0; nt < 4; nt++) {
                    int col = n0 + wn + nt * 8 + (lane & 3) * 2;
                    float b0 = bias[col], b1 = bias[col + 1];
                    float2 o0 = make_float2(acc[mt][nt][0] + b0, acc[mt][nt][1] + b1);
                    float2 o1 = make_float2(acc[mt][nt][2] + b0, acc[mt][nt][3] + b1);
                    if (RELU) {
                        o0.x = fmaxf(o0.x, 0.f); o0.y = fmaxf(o0.y, 0.f);
                        o1.x = fmaxf(o1.x, 0.f); o1.y = fmaxf(o1.y, 0.f);
                    }
                    if (row < M)     *(float2*)(C + (size_t)row * N + col) = o0;
                    if (row + 8 < M) *(float2*)(C + (size_t)(row + 8) * N + col) = o1;
                }
            }
            if (STATS) {
#pragma unroll
                for (int nt = 0; nt < 4; nt++) {
                    int colr = wn + nt * 8 + (lane & 3) * 2;
                    float b0 = bias[n0 + colr], b1 = bias[n0 + colr + 1];
                    float s0 = 0.f, s1 = 0.f, q0 = 0.f, q1 = 0.f;
#pragma unroll
                    for (int mt = 0; mt < 2; mt++) {
                        int r = m0 + wm + mt * 16 + (lane >> 2);
                        float ok0 = (r < M) ? 1.f : 0.f;
                        float ok1 = (r + 8 < M) ? 1.f : 0.f;
                        float v00 = (acc[mt][nt][0] + b0) * ok0;
                        float v01 = (acc[mt][nt][1] + b1) * ok0;
                        float v10 = (acc[mt][nt][2] + b0) * ok1;
                        float v11 = (acc[mt][nt][3] + b1) * ok1;
                        s0 += v00 + v10; s1 += v01 + v11;
                        q0 += v00 * v00 + v10 * v10;
                        q1 += v01 * v01 + v11 * v11;
                    }
#pragma unroll
                    for (int d = 4; d < 32; d <<= 1) {
                        s0 += __shfl_xor_sync(0xFFFFFFFFu, s0, d);
                        s1 += __shfl_xor_sync(0xFFFFFFFFu, s1, d);
                        q0 += __shfl_xor_sync(0xFFFFFFFFu, q0, d);
                        q1 += __shfl_xor_sync(0xFFFFFFFFu, q1, d);
                    }
                    if (lane < 4) {
                        atomicAdd(&ssum[colr], s0);
                        atomicAdd(&ssum[colr + 1], s1);
                        atomicAdd(&ssum[128 + colr], q0);
                        atomicAdd(&ssum[128 + colr + 1], q1);
                    }
                }
                __syncthreads();
                if (tid < 128)       atomicAdd(&gs[n0 + tid], ssum[tid]);
                else if (tid < 256)  atomicAdd(&gq[n0 + tid - 128], ssum[tid]);
            }
            // reset accumulators for next subtile
#pragma unroll
            for (int i = 0; i < 2; i++)
#pragma unroll
                for (int j = 0; j < 4; j++)
#pragma unroll
                    for (int q = 0; q < 4; q++) acc[i][j][q] = 0.f;
        }
    }
}

// ---------------- final layer ----------------
__global__ __launch_bounds__(256)
void final_kernel(const float* __restrict__ g3,
                  const float* __restrict__ sc, const float* __restrict__ sh,
                  const float* __restrict__ hw4, const float* __restrict__ hb4,
                  float* __restrict__ pen, float* __restrict__ logits) {
    __shared__ float w4s[256 * 16];
    __shared__ float at[16 * 256];
    int t = threadIdx.x;
    for (int i = t; i < 4096; i += 256) w4s[i] = hw4[i];
    long long r0 = (long long)blockIdx.x * 16;
#pragma unroll
    for (int i = 0; i < 16; i++) {
        float v = g3[(r0 + i) * 256 + t];
        v = fmaxf(fmaf(v, sc[t], sh[t]), 0.f);
        at[i * 256 + t] = v;
        pen[(r0 + i) * 256 + t] = v;
    }
    __syncthreads();
    int r = t >> 4, c = t & 15;
    float acc = hb4[c];
#pragma unroll 8
    for (int k = 0; k < 256; k++)
        acc = fmaf(at[r * 256 + k], w4s[k * 16 + c], acc);
    logits[(r0 + r) * 16 + c] = acc;
}

// ---------------- launch ----------------
extern "C" void kernel_launch(void* const* d_in, const int* in_sizes, int n_in,
                              void* d_out, int out_size) {
    const float* x   = (const float*)d_in[0];
    const void*  ei  = d_in[1];
    const float* w1  = (const float*)d_in[2];
    const float* b1  = (const float*)d_in[3];
    const float* wl  = (const float*)d_in[4];
    const float* bl  = (const float*)d_in[5];
    const float* wr  = (const float*)d_in[6];
    const float* hw1 = (const float*)d_in[7];
    const float* hb1 = (const float*)d_in[8];
    const float* ga1 = (const float*)d_in[9];
    const float* be1 = (const float*)d_in[10];
    const float* hw2 = (const float*)d_in[11];
    const float* hb2 = (const float*)d_in[12];
    const float* ga2 = (const float*)d_in[13];
    const float* be2 = (const float*)d_in[14];
    const float* hw3 = (const float*)d_in[15];
    const float* hb3 = (const float*)d_in[16];
    const float* ga3 = (const float*)d_in[17];
    const float* be3 = (const float*)d_in[18];
    const float* hw4 = (const float*)d_in[19];
    const float* hb4 = (const float*)d_in[20];

    float* out_logits = (float*)d_out;
    float* out_pen    = (float*)d_out + (size_t)NN * 16;
    float* out_feat   = (float*)d_out + (size_t)NN * (16 + 256);

    float *h0, *sums, *cnt, *p1, *p2, *p3, *sc, *sh, *cs, *cq;
    __nv_bfloat16 *b1p, *b2p, *b3p, *b4p, *b5p;
    int* nz;
    cudaGetSymbolAddress((void**)&h0,   g_h0);
    cudaGetSymbolAddress((void**)&sums, g_sums);
    cudaGetSymbolAddress((void**)&cnt,  g_cnt);
    cudaGetSymbolAddress((void**)&p1,   g_p1);
    cudaGetSymbolAddress((void**)&p2,   g_p2);
    cudaGetSymbolAddress((void**)&p3,   g_p3);
    cudaGetSymbolAddress((void**)&sc,   g_scale);
    cudaGetSymbolAddress((void**)&sh,   g_shift);
    cudaGetSymbolAddress((void**)&cs,   g_cs);
    cudaGetSymbolAddress((void**)&cq,   g_cq);
    cudaGetSymbolAddress((void**)&nz,   g_nz);
    cudaGetSymbolAddress((void**)&b1p, g_b1);
    cudaGetSymbolAddress((void**)&b2p, g_b2);
    cudaGetSymbolAddress((void**)&b3p, g_b3);
    cudaGetSymbolAddress((void**)&b4p, g_b4);
    cudaGetSymbolAddress((void**)&b5p, g_b5);

    const int M = NN;
    const int MTS = (M + 128 * NSUB - 1) / (128 * NSUB);   // 196
    dim3 blk(256);
    dim3 gblk(GTH);

    cudaFuncSetAttribute(mgemm<0,1,0>, cudaFuncAttributeMaxDynamicSharedMemorySize, DSM_BYTES);
    cudaFuncSetAttribute(mgemm<2,0,0>, cudaFuncAttributeMaxDynamicSharedMemorySize, DSM_BYTES);
    cudaFuncSetAttribute(mgemm<0,0,1>, cudaFuncAttributeMaxDynamicSharedMemorySize, DSM_BYTES);
    cudaFuncSetAttribute(mgemm<1,0,1>, cudaFuncAttributeMaxDynamicSharedMemorySize, DSM_BYTES);

    // nz pre-zero (memset op, not a kernel launch)
    cudaMemsetAsync(nz, 0, sizeof(int));
    // 0: zero everything + dtype detect
    {
        int total = NN * 128 + NN + 1536 * 4 + 16384 * 4;
        zero_all<<<(total / 4 + 255) / 256, blk>>>(sums, cnt, cs, cq,
                                                   (const unsigned int*)ei, nz);
    }
    // 1: all weight packs
    tsplit_all<<<(598016 + 255) / 256, blk>>>(w1, wl, wr, hw1, hw2, hw3,
                                              b1p, b2p, b3p, b4p, b5p);
    // 2: G1
    mgemm<0,1,0><<<dim3(1, MTS), gblk, DSM_BYTES>>>(x, b1p, b1, h0, M, 64, 128,
        nullptr, nullptr, nullptr, nullptr, nullptr, nullptr);
    // 3: edge scatter  (ncu capture slot)
    edge_kernel<<<EE / 64, blk>>>(ei, h0, sums, cnt, nz);
    // 4: G2
    mgemm<2,0,0><<<dim3(1, MTS), gblk, DSM_BYTES>>>(sums, b2p, bl, out_feat, M, 256, 128,
        nullptr, nullptr, h0, cnt, nullptr, nullptr);
    // 5: G3 (+stats slice 0)
    mgemm<0,0,1><<<dim3(2, MTS), gblk, DSM_BYTES>>>(out_feat, b3p, hb1, p1, M, 128, 256,
        nullptr, nullptr, nullptr, nullptr, cs, cq);
    // 6
    fin_bn<<<1, 256>>>(cs, cq, ga1, be1, sc, sh, 256);
    // 7: G4 (+stats slice 1)
    mgemm<1,0,1><<<dim3(8, MTS), gblk, DSM_BYTES>>>(p1, b4p, hb2, p2, M, 256, 1024,
        sc, sh, nullptr, nullptr, cs + 256, cq + 256);
    // 8
    fin_bn<<<4, 256>>>(cs + 256, cq + 256, ga2, be2, sc, sh, 1024);
    // 9: G5 (+stats slice 2)
    mgemm<1,0,1><<<dim3(2, MTS), gblk, DSM_BYTES>>>(p2, b5p, hb3, p3, M, 1024, 256,
        sc, sh, nullptr, nullptr, cs + 1280, cq + 1280);
    // 10
    fin_bn<<<1, 256>>>(cs + 1280, cq + 1280, ga3, be3, sc, sh, 256);
    // 11: final
    final_kernel<<<NN / 16, blk>>>(p3, sc, sh, hw4, hb4, out_pen, out_logits);
}

// round 12
// speedup vs baseline: 1.0228x; 1.0228x over previous
#include <cuda_runtime.h>
#include <cuda_bf16.h>
#include <cstdint>

// ---------------- problem constants ----------------
#define NN 100000
#define EE 1600000

// ---------------- scratch (device globals) ----------------
__device__ float  g_h0[(size_t)NN * 128];
__device__ float  g_sums[(size_t)NN * 128];
__device__ float  g_cnt[NN];
__device__ float  g_p1[(size_t)NN * 256];
__device__ float  g_p2[(size_t)NN * 1024];
__device__ float  g_p3[(size_t)NN * 256];
__device__ float  g_cs[1536];      // stats slices: L1 @0(256), L2 @256(1024), L3 @1280(256)
__device__ float  g_cq[1536];
__device__ float  g_scale[1024];
__device__ float  g_shift[1024];
__device__ int    g_nz;            // nonzero high words -> edges are int32
// packed split weights: [N][K/32][64] halves, chunk = [hi(32) | lo(32)]
__device__ __nv_bfloat16 g_b1[128 * 64 * 2];
__device__ __nv_bfloat16 g_b2[128 * 256 * 2];
__device__ __nv_bfloat16 g_b3[256 * 128 * 2];
__device__ __nv_bfloat16 g_b4[1024 * 256 * 2];
__device__ __nv_bfloat16 g_b5[256 * 1024 * 2];

// ---------------- helpers ----------------
__device__ __forceinline__ uint32_t smem_u32(const void* p) {
    uint32_t a;
    asm("{ .reg .u64 t; cvta.to.shared.u64 t, %1; cvt.u32.u64 %0, t; }" : "=r"(a) : "l"(p));
    return a;
}
#define LDSM4(R, addr) \
    asm volatile("ldmatrix.sync.aligned.m8n8.x4.shared.b16 {%0,%1,%2,%3}, [%4];" \
        : "=r"((R)[0]), "=r"((R)[1]), "=r"((R)[2]), "=r"((R)[3]) : "r"(addr))

__device__ __forceinline__ void mma_bf16(float* c, const uint32_t* a, const uint32_t* b) {
    asm volatile("mma.sync.aligned.m16n8k16.row.col.f32.bf16.bf16.f32 "
        "{%0,%1,%2,%3}, {%4,%5,%6,%7}, {%8,%9}, {%0,%1,%2,%3};"
        : "+f"(c[0]), "+f"(c[1]), "+f"(c[2]), "+f"(c[3])
        : "r"(a[0]), "r"(a[1]), "r"(a[2]), "r"(a[3]), "r"(b[0]), "r"(b[1]));
}
#define CP_A16(dst, src) \
    asm volatile("cp.async.ca.shared.global [%0], [%1], 16;" :: "r"(dst), "l"(src))
#define CP_COMMIT()  asm volatile("cp.async.commit_group;")
#define CP_WAIT0()   asm volatile("cp.async.wait_group 0;")
#define CP_WAIT1()   asm volatile("cp.async.wait_group 1;")

__device__ __forceinline__ void split_bf(float v, uint16_t& h, uint16_t& l) {
    __nv_bfloat16 hb = __float2bfloat16(v);
    __nv_bfloat16 lb = __float2bfloat16(v - __bfloat162float(hb));
    h = __bfloat16_as_ushort(hb);
    l = __bfloat16_as_ushort(lb);
}

// ---------------- merged prep kernels ----------------
// zero_all: sums (NN*128), cnt (NN), cs/cq (2x1536) + edge dtype detect.
// nz must be pre-zeroed (cudaMemsetAsync) before this kernel.
__global__ void zero_all(float* sums, float* cnt, float* cs, float* cq,
                         const unsigned int* ew, int* nz) {
    int i = (blockIdx.x * blockDim.x + threadIdx.x) * 4;
    const int n_sums = NN * 128;
    if (i < n_sums) {
        *(float4*)(sums + i) = make_float4(0.f, 0.f, 0.f, 0.f);
    } else {
        int j = i - n_sums;
        if (j < NN) {
            for (int q = 0; q < 4 && j + q < NN; q++) cnt[j + q] = 0.f;
        } else if (j < NN + 1536) {
            int s = j - NN;
            *(float4*)(cs + s) = make_float4(0.f, 0.f, 0.f, 0.f);
            *(float4*)(cq + s) = make_float4(0.f, 0.f, 0.f, 0.f);
        } else {
            int d = j - NN - 1536;      // detect range: d in [0, 16384), 4 checks each
            if (d < 16384) {
                unsigned int bad = 0;
                for (int q = 0; q < 4; q++) bad |= ew[2 * (d + q) + 1];
                unsigned int any = __ballot_sync(__activemask(), bad != 0u);
                if (any && (threadIdx.x & 31) == (__ffs(any) - 1)) atomicOr(nz, 1);
            }
        }
    }
}
__global__ void tsplit_all(const float* __restrict__ w1, const float* __restrict__ wl,
                           const float* __restrict__ wr, const float* __restrict__ hw1,
                           const float* __restrict__ hw2, const float* __restrict__ hw3,
                           __nv_bfloat16* b1, __nv_bfloat16* b2, __nv_bfloat16* b3,
                           __nv_bfloat16* b4, __nv_bfloat16* b5) {
    int idx = blockIdx.x * blockDim.x + threadIdx.x;
    const float* W; __nv_bfloat16* bp; int K, N; int local;
    if (idx < 8192)        { local = idx;          W = w1;  bp = b1; K = 64;   N = 128; }
    else if (idx < 40960)  { local = idx - 8192;   W = nullptr; bp = b2; K = 256; N = 128; }
    else if (idx < 73728)  { local = idx - 40960;  W = hw1; bp = b3; K = 128;  N = 256; }
    else if (idx < 335872) { local = idx - 73728;  W = hw2; bp = b4; K = 256;  N = 1024; }
    else if (idx < 598016) { local = idx - 335872; W = hw3; bp = b5; K = 1024; N = 256; }
    else return;
    int n = local / K, k = local % K;
    float v;
    if (W) v = W[(size_t)k * N + n];
    else   v = (k < 128) ? wl[k * 128 + n] : wr[(k - 128) * 128 + n];
    uint16_t h, l;
    split_bf(v, h, l);
    size_t base = ((size_t)n * (K >> 5) + (k >> 5)) * 64 + (k & 31);
    bp[base] = __ushort_as_bfloat16(h);
    bp[base + 32] = __ushort_as_bfloat16(l);
}

// ---------------- edge scatter (8 edges per warp) ----------------
__global__ void edge_kernel(const void* __restrict__ ei, const float* __restrict__ h0,
                            float* __restrict__ sums, float* __restrict__ cnt,
                            const int* __restrict__ nz) {
    int warp0 = ((blockIdx.x * blockDim.x + threadIdx.x) >> 5) * 8;
    int lane = threadIdx.x & 31;
    const int is64 = (*nz == 0);
#pragma unroll
    for (int e = warp0; e < warp0 + 8; e++) {
        long long src, dst;
        if (is64) {
            const long long* p = (const long long*)ei;
            src = p[e]; dst = p[EE + e];
        } else {
            const int* p = (const int*)ei;
            src = p[e]; dst = p[EE + e];
        }
        float4 v = *(const float4*)(h0 + src * 128 + lane * 4);
        float* d = sums + dst * 128 + lane * 4;
        asm volatile("red.global.add.v4.f32 [%0], {%1, %2, %3, %4};"
                     :: "l"(d), "f"(v.x), "f"(v.y), "f"(v.z), "f"(v.w) : "memory");
        if (lane == 0) atomicAdd(cnt + dst, 1.0f);
    }
}

__global__ void fin_bn(const float* __restrict__ cs, const float* __restrict__ cq,
                       const float* __restrict__ gm, const float* __restrict__ bt,
                       float* __restrict__ sc, float* __restrict__ sh, int ncols) {
    int c = blockIdx.x * blockDim.x + threadIdx.x;
    if (c < ncols) {
        double mean = (double)cs[c] * (1.0 / (double)NN);
        double var  = (double)cq[c] * (1.0 / (double)NN) - mean * mean;
        if (var < 0.0) var = 0.0;
        float rstd = (float)(1.0 / sqrt(var + 1e-5));
        float s = gm[c] * rstd;
        sc[c] = s;
        sh[c] = bt[c] - (float)mean * s;
    }
}

// ---------------- pipelined mma.sync bf16x3 GEMM (BK=64, 512 thr) ----------
// SUB M-subtiles of 128 rows per CTA (SUB=1: round-10 behavior).
// MODE 0: plain | MODE 1: relu(a*sc+sh) | MODE 2: k<128: A(sums)/cnt; else aux
#define DSM_BYTES 131072
#define GTH 512

template<int MODE, int RELU, int STATS, int SUB>
__global__ void __launch_bounds__(GTH, 1)
mgemm(const float* __restrict__ A, const __nv_bfloat16* __restrict__ Bpk,
      const float* __restrict__ bias, float* __restrict__ C,
      int M, int K, int N,
      const float* __restrict__ sc, const float* __restrict__ sh,
      const float* __restrict__ aux, const float* __restrict__ cnt,
      float* __restrict__ gs, float* __restrict__ gq) {
    extern __shared__ __align__(16) char dsm[];
    __shared__ float ssum[256];
    char* sAc = dsm;
    const uint32_t sA_b = smem_u32(dsm);
    const uint32_t sB_b = sA_b + 65536;

    const int tid = threadIdx.x, lane = tid & 31, wid = tid >> 5;
    const int wm = (wid & 3) * 32, wn = (wid >> 2) * 32;
    const int n0 = blockIdx.x * 128;
    const int nch = K >> 6;               // power of 2: 1,2,4,16
    const int lg = 31 - __clz(nch);
    const int kc32 = K >> 5;
    const int T = nch * SUB;

    float acc[2][4][4];
#pragma unroll
    for (int i = 0; i < 2; i++)
#pragma unroll
        for (int j = 0; j < 4; j++)
#pragma unroll
            for (int q = 0; q < 4; q++) acc[i][j][q] = 0.f;

    auto m0_of = [&](int t) { return (blockIdx.y * SUB + (t >> lg)) * 128; };

    auto issueB = [&](int t) {
        const int buf = t & 1;
        const int c = t & (nch - 1);
        const uint32_t bb = sB_b + buf * 32768;
#pragma unroll
        for (int l = 0; l < 4; l++) {
            int pos = tid + l * GTH;
            int row = pos >> 4, q = pos & 15;
            const char* srcB = (const char*)(Bpk + ((size_t)(n0 + row) * kc32 + 2 * c) * 64) + q * 16;
            uint32_t dst = bb + row * 256 + (uint32_t)((q >> 3) * 128)
                         + (((uint32_t)((q & 7) * 16)) ^ (uint32_t)((row & 7) * 16));
            CP_A16(dst, srcB);
        }
        CP_COMMIT();
    };

    auto load_A = [&](int t, float4* rv) {
        const int k0 = (t & (nch - 1)) << 6;
        const int m0 = m0_of(t);
#pragma unroll
        for (int l = 0; l < 4; l++) {
            int pos = tid + l * GTH;
            int row = pos >> 4, q = pos & 15;
            int grow = m0 + row;
            float4 v = make_float4(0.f, 0.f, 0.f, 0.f);
            if (grow < M) {
                if (MODE == 2) {
                    if (k0 < 128) v = *(const float4*)(A + (size_t)grow * 128 + k0 + q * 4);
                    else          v = *(const float4*)(aux + (size_t)grow * 128 + (k0 - 128) + q * 4);
                } else {
                    v = *(const float4*)(A + (size_t)grow * K + k0 + q * 4);
                }
            }
            rv[l] = v;
        }
    };
    // (row, q) quad covers k = q*4..q*4+3 -> group (q>>3), in-group byte (q&7)*8
    auto split_store = [&](int t, float4* rv) {
        const int buf = t & 1;
        const int k0 = (t & (nch - 1)) << 6;
        const int m0 = m0_of(t);
        char* sAd = sAc + buf * 32768;
#pragma unroll
        for (int l = 0; l < 4; l++) {
            int pos = tid + l * GTH;
            int row = pos >> 4, q = pos & 15;
            int grow = m0 + row;
            float4 v = rv[l];
            if (MODE == 1) {
                float4 s4 = *(const float4*)(sc + k0 + q * 4);
                float4 h4 = *(const float4*)(sh + k0 + q * 4);
                v.x = fmaxf(fmaf(v.x, s4.x, h4.x), 0.f);
                v.y = fmaxf(fmaf(v.y, s4.y, h4.y), 0.f);
                v.z = fmaxf(fmaf(v.z, s4.z, h4.z), 0.f);
                v.w = fmaxf(fmaf(v.w, s4.w, h4.w), 0.f);
            }
            if (MODE == 2 && k0 < 128) {
                float cv = (grow < M) ? cnt[grow] : 1.f;
                float ic = 1.f / fmaxf(cv, 1.f);
                v.x *= ic; v.y *= ic; v.z *= ic; v.w *= ic;
            }
            uint16_t hx, hy, hz, hw_, lx, ly, lz, lw;
            split_bf(v.x, hx, lx); split_bf(v.y, hy, ly);
            split_bf(v.z, hz, lz); split_bf(v.w, hw_, lw);
            uint2 hi2 = make_uint2((uint32_t)hx | ((uint32_t)hy << 16),
                                   (uint32_t)hz | ((uint32_t)hw_ << 16));
            uint2 lo2 = make_uint2((uint32_t)lx | ((uint32_t)ly << 16),
                                   (uint32_t)lz | ((uint32_t)lw << 16));
            uint32_t xr = (uint32_t)((row & 7) * 16);
            uint32_t base = (uint32_t)(row * 256 + (q >> 3) * 128);
            uint32_t qq = (uint32_t)((q & 7) * 8);
            *(uint2*)(sAd + base + (qq ^ xr)) = hi2;
            *(uint2*)(sAd + base + ((64 + qq) ^ xr)) = lo2;
        }
    };

    // ---- prologue ----
    issueB(0);
    if (T > 1) issueB(1);
    {
        float4 rv0[4];
        load_A(0, rv0);
        split_store(0, rv0);
    }
    if (T > 1) CP_WAIT1(); else CP_WAIT0();
    __syncthreads();

    // ---- mainloop across SUB subtiles, one barrier per chunk ----
    for (int t = 0; t < T; t++) {
        const int buf = t & 1;
        float4 rv[4];
        if (t + 1 < T) load_A(t + 1, rv);
        const uint32_t ab = sA_b + buf * 32768;
        const uint32_t bb = sB_b + buf * 32768;
#pragma unroll
        for (int ks = 0; ks < 4; ks++) {
            const uint32_t gb = (uint32_t)((ks >> 1) * 128);
            const uint32_t kb = (uint32_t)((ks & 1) * 32);
            uint32_t afh[2][4], afl[2][4];
#pragma unroll
            for (int mt = 0; mt < 2; mt++) {
                int row = wm + mt * 16 + (lane & 15);
                uint32_t cb = kb + (uint32_t)((lane >> 4) * 16);
                uint32_t x = (uint32_t)((row & 7) * 16);
                uint32_t rb = ab + row * 256 + gb;
                LDSM4(afh[mt], rb + (cb ^ x));
                LDSM4(afl[mt], rb + ((cb + 64) ^ x));
            }
            uint32_t bfh[2][4], bfl[2][4];
#pragma unroll
            for (int np = 0; np < 2; np++) {
                int row = wn + np * 16 + (lane & 7) + ((lane >> 4) & 1) * 8;
                uint32_t cb = kb + (uint32_t)(((lane >> 3) & 1) * 16);
                uint32_t x = (uint32_t)((row & 7) * 16);
                uint32_t rb = bb + row * 256 + gb;
                LDSM4(bfh[np], rb + (cb ^ x));
                LDSM4(bfl[np], rb + ((cb + 64) ^ x));
            }
#pragma unroll
            for (int mt = 0; mt < 2; mt++)
#pragma unroll
                for (int np = 0; np < 2; np++)
#pragma unroll
                    for (int sub = 0; sub < 2; sub++) {
                        int nt = np * 2 + sub;
                        mma_bf16(acc[mt][nt], afh[mt], &bfh[np][sub * 2]);
                        mma_bf16(acc[mt][nt], afl[mt], &bfh[np][sub * 2]);
                        mma_bf16(acc[mt][nt], afh[mt], &bfl[np][sub * 2]);
                    }
        }
        if (t + 1 < T) {
            split_store(t + 1, rv);
            CP_WAIT0();
        }
        __syncthreads();
        if (t + 2 < T) issueB(t + 2);

        // ---- subtile epilogue ----
        if ((t & (nch - 1)) == nch - 1) {
            const int m0 = m0_of(t);
            if (STATS) {
                if (tid < 256) ssum[tid] = 0.f;
                __syncthreads();
            }
#pragma unroll
            for (int mt = 0; mt < 2; mt++) {
                int row = m0 + wm + mt * 16 + (lane >> 2);
#pragma unroll
                for (int nt = 0; nt < 4; nt++) {
                    int col = n0 + wn + nt * 8 + (lane & 3) * 2;
                    float b0 = bias[col], b1 = bias[col + 1];
                    float2 o0 = make_float2(acc[mt][nt][0] + b0, acc[mt][nt][1] + b1);
                    float2 o1 = make_float2(acc[mt][nt][2] + b0, acc[mt][nt][3] + b1);
                    if (RELU) {
                        o0.x = fmaxf(o0.x, 0.f); o0.y = fmaxf(o0.y, 0.f);
                        o1.x = fmaxf(o1.x, 0.f); o1.y = fmaxf(o1.y, 0.f);
                    }
                    if (row < M)     *(float2*)(C + (size_t)row * N + col) = o0;
                    if (row + 8 < M) *(float2*)(C + (size_t)(row + 8) * N + col) = o1;
                }
            }
            if (STATS) {
#pragma unroll
                for (int nt = 0; nt < 4; nt++) {
                    int colr = wn + nt * 8 + (lane & 3) * 2;
                    float b0 = bias[n0 + colr], b1 = bias[n0 + colr + 1];
                    float s0 = 0.f, s1 = 0.f, q0 = 0.f, q1 = 0.f;
#pragma unroll
                    for (int mt = 0; mt < 2; mt++) {
                        int r = m0 + wm + mt * 16 + (lane >> 2);
                        float ok0 = (r < M) ? 1.f : 0.f;
                        float ok1 = (r + 8 < M) ? 1.f : 0.f;
                        float v00 = (acc[mt][nt][0] + b0) * ok0;
                        float v01 = (acc[mt][nt][1] + b1) * ok0;
                        float v10 = (acc[mt][nt][2] + b0) * ok1;
                        float v11 = (acc[mt][nt][3] + b1) * ok1;
                        s0 += v00 + v10; s1 += v01 + v11;
                        q0 += v00 * v00 + v10 * v10;
                        q1 += v01 * v01 + v11 * v11;
                    }
#pragma unroll
                    for (int d = 4; d < 32; d <<= 1) {
                        s0 += __shfl_xor_sync(0xFFFFFFFFu, s0, d);
                        s1 += __shfl_xor_sync(0xFFFFFFFFu, s1, d);
                        q0 += __shfl_xor_sync(0xFFFFFFFFu, q0, d);
                        q1 += __shfl_xor_sync(0xFFFFFFFFu, q1, d);
                    }
                    if (lane < 4) {
                        atomicAdd(&ssum[colr], s0);
                        atomicAdd(&ssum[colr + 1], s1);
                        atomicAdd(&ssum[128 + colr], q0);
                        atomicAdd(&ssum[128 + colr + 1], q1);
                    }
                }
                __syncthreads();
                if (tid < 128)       atomicAdd(&gs[n0 + tid], ssum[tid]);
                else if (tid < 256)  atomicAdd(&gq[n0 + tid - 128], ssum[tid]);
            }
            if (t + 1 < T) {
#pragma unroll
                for (int i = 0; i < 2; i++)
#pragma unroll
                    for (int j = 0; j < 4; j++)
#pragma unroll
                        for (int q = 0; q < 4; q++) acc[i][j][q] = 0.f;
            }
        }
    }
}

// ---------------- final layer ----------------
__global__ __launch_bounds__(256)
void final_kernel(const float* __restrict__ g3,
                  const float* __restrict__ sc, const float* __restrict__ sh,
                  const float* __restrict__ hw4, const float* __restrict__ hb4,
                  float* __restrict__ pen, float* __restrict__ logits) {
    __shared__ float w4s[256 * 16];
    __shared__ float at[16 * 256];
    int t = threadIdx.x;
    for (int i = t; i < 4096; i += 256) w4s[i] = hw4[i];
    long long r0 = (long long)blockIdx.x * 16;
#pragma unroll
    for (int i = 0; i < 16; i++) {
        float v = g3[(r0 + i) * 256 + t];
        v = fmaxf(fmaf(v, sc[t], sh[t]), 0.f);
        at[i * 256 + t] = v;
        pen[(r0 + i) * 256 + t] = v;
    }
    __syncthreads();
    int r = t >> 4, c = t & 15;
    float acc = hb4[c];
#pragma unroll 8
    for (int k = 0; k < 256; k++)
        acc = fmaf(at[r * 256 + k], w4s[k * 16 + c], acc);
    logits[(r0 + r) * 16 + c] = acc;
}

// ---------------- launch ----------------
extern "C" void kernel_launch(void* const* d_in, const int* in_sizes, int n_in,
                              void* d_out, int out_size) {
    const float* x   = (const float*)d_in[0];
    const void*  ei  = d_in[1];
    const float* w1  = (const float*)d_in[2];
    const float* b1  = (const float*)d_in[3];
    const float* wl  = (const float*)d_in[4];
    const float* bl  = (const float*)d_in[5];
    const float* wr  = (const float*)d_in[6];
    const float* hw1 = (const float*)d_in[7];
    const float* hb1 = (const float*)d_in[8];
    const float* ga1 = (const float*)d_in[9];
    const float* be1 = (const float*)d_in[10];
    const float* hw2 = (const float*)d_in[11];
    const float* hb2 = (const float*)d_in[12];
    const float* ga2 = (const float*)d_in[13];
    const float* be2 = (const float*)d_in[14];
    const float* hw3 = (const float*)d_in[15];
    const float* hb3 = (const float*)d_in[16];
    const float* ga3 = (const float*)d_in[17];
    const float* be3 = (const float*)d_in[18];
    const float* hw4 = (const float*)d_in[19];
    const float* hb4 = (const float*)d_in[20];

    float* out_logits = (float*)d_out;
    float* out_pen    = (float*)d_out + (size_t)NN * 16;
    float* out_feat   = (float*)d_out + (size_t)NN * (16 + 256);

    float *h0, *sums, *cnt, *p1, *p2, *p3, *sc, *sh, *cs, *cq;
    __nv_bfloat16 *b1p, *b2p, *b3p, *b4p, *b5p;
    int* nz;
    cudaGetSymbolAddress((void**)&h0,   g_h0);
    cudaGetSymbolAddress((void**)&sums, g_sums);
    cudaGetSymbolAddress((void**)&cnt,  g_cnt);
    cudaGetSymbolAddress((void**)&p1,   g_p1);
    cudaGetSymbolAddress((void**)&p2,   g_p2);
    cudaGetSymbolAddress((void**)&p3,   g_p3);
    cudaGetSymbolAddress((void**)&sc,   g_scale);
    cudaGetSymbolAddress((void**)&sh,   g_shift);
    cudaGetSymbolAddress((void**)&cs,   g_cs);
    cudaGetSymbolAddress((void**)&cq,   g_cq);
    cudaGetSymbolAddress((void**)&nz,   g_nz);
    cudaGetSymbolAddress((void**)&b1p, g_b1);
    cudaGetSymbolAddress((void**)&b2p, g_b2);
    cudaGetSymbolAddress((void**)&b3p, g_b3);
    cudaGetSymbolAddress((void**)&b4p, g_b4);
    cudaGetSymbolAddress((void**)&b5p, g_b5);

    const int M = NN;
    const int MT1 = (M + 127) / 128;              // 782 (SUB=1)
    const int MT4 = (M + 128 * 4 - 1) / (128 * 4); // 196 (SUB=4)
    dim3 blk(256);
    dim3 gblk(GTH);

    cudaFuncSetAttribute(mgemm<0,1,0,1>, cudaFuncAttributeMaxDynamicSharedMemorySize, DSM_BYTES);
    cudaFuncSetAttribute(mgemm<2,0,0,1>, cudaFuncAttributeMaxDynamicSharedMemorySize, DSM_BYTES);
    cudaFuncSetAttribute(mgemm<0,0,1,1>, cudaFuncAttributeMaxDynamicSharedMemorySize, DSM_BYTES);
    cudaFuncSetAttribute(mgemm<1,0,1,4>, cudaFuncAttributeMaxDynamicSharedMemorySize, DSM_BYTES);
    cudaFuncSetAttribute(mgemm<1,0,1,1>, cudaFuncAttributeMaxDynamicSharedMemorySize, DSM_BYTES);

    // nz pre-zero (memset op, not a kernel launch)
    cudaMemsetAsync(nz, 0, sizeof(int));
    // 0: zero everything + dtype detect
    {
        int total = NN * 128 + NN + 1536 * 4 + 16384 * 4;
        zero_all<<<(total / 4 + 255) / 256, blk>>>(sums, cnt, cs, cq,
                                                   (const unsigned int*)ei, nz);
    }
    // 1: all weight packs
    tsplit_all<<<(598016 + 255) / 256, blk>>>(w1, wl, wr, hw1, hw2, hw3,
                                              b1p, b2p, b3p, b4p, b5p);
    // 2: G1
    mgemm<0,1,0,1><<<dim3(1, MT1), gblk, DSM_BYTES>>>(x, b1p, b1, h0, M, 64, 128,
        nullptr, nullptr, nullptr, nullptr, nullptr, nullptr);
    // 3: edge scatter
    edge_kernel<<<EE / 64, blk>>>(ei, h0, sums, cnt, nz);
    // 4: G2
    mgemm<2,0,0,1><<<dim3(1, MT1), gblk, DSM_BYTES>>>(sums, b2p, bl, out_feat, M, 256, 128,
        nullptr, nullptr, h0, cnt, nullptr, nullptr);
    // 5: G3 (+stats slice 0)
    mgemm<0,0,1,1><<<dim3(2, MT1), gblk, DSM_BYTES>>>(out_feat, b3p, hb1, p1, M, 128, 256,
        nullptr, nullptr, nullptr, nullptr, cs, cq);
    // 6
    fin_bn<<<1, 256>>>(cs, cq, ga1, be1, sc, sh, 256);
    // 7: G4 (+stats slice 1)  -- SUB=4 persistence (grid stays 8x196 = 10.6 waves)
    mgemm<1,0,1,4><<<dim3(8, MT4), gblk, DSM_BYTES>>>(p1, b4p, hb2, p2, M, 256, 1024,
        sc, sh, nullptr, nullptr, cs + 256, cq + 256);
    // 8
    fin_bn<<<4, 256>>>(cs + 256, cq + 256, ga2, be2, sc, sh, 1024);
    // 9: G5 (+stats slice 2)
    mgemm<1,0,1,1><<<dim3(2, MT1), gblk, DSM_BYTES>>>(p2, b5p, hb3, p3, M, 1024, 256,
        sc, sh, nullptr, nullptr, cs + 1280, cq + 1280);
    // 10
    fin_bn<<<1, 256>>>(cs + 1280, cq + 1280, ga3, be3, sc, sh, 256);
    // 11: final
    final_kernel<<<NN / 16, blk>>>(p3, sc, sh, hw4, hb4, out_pen, out_logits);
}

// round 13
// speedup vs baseline: 1.0805x; 1.0564x over previous
#include <cuda_runtime.h>
#include <cuda_bf16.h>
#include <cstdint>

// ---------------- problem constants ----------------
#define NN 100000
#define EE 1600000

// ---------------- scratch (device globals) ----------------
__device__ float  g_h0[(size_t)NN * 128];
__device__ float  g_sums[(size_t)NN * 128];
__device__ float  g_cnt[NN];
__device__ float  g_p1[(size_t)NN * 256];
__device__ float  g_p2[(size_t)NN * 1024];
__device__ float  g_p3[(size_t)NN * 256];
__device__ float  g_cs[1536];      // stats slices: L1 @0(256), L2 @256(1024), L3 @1280(256)
__device__ float  g_cq[1536];
__device__ float  g_scale[1024];
__device__ float  g_shift[1024];
__device__ int    g_nz;            // nonzero high words -> edges are int32
// packed split weights: [N][K/32][64] halves, chunk = [hi(32) | lo(32)]
__device__ __nv_bfloat16 g_b1[128 * 64 * 2];
__device__ __nv_bfloat16 g_b2[128 * 256 * 2];
__device__ __nv_bfloat16 g_b3[256 * 128 * 2];
__device__ __nv_bfloat16 g_b4[1024 * 256 * 2];
__device__ __nv_bfloat16 g_b5[256 * 1024 * 2];

// ---------------- helpers ----------------
__device__ __forceinline__ uint32_t smem_u32(const void* p) {
    uint32_t a;
    asm("{ .reg .u64 t; cvta.to.shared.u64 t, %1; cvt.u32.u64 %0, t; }" : "=r"(a) : "l"(p));
    return a;
}
#define LDSM4(R, addr) \
    asm volatile("ldmatrix.sync.aligned.m8n8.x4.shared.b16 {%0,%1,%2,%3}, [%4];" \
        : "=r"((R)[0]), "=r"((R)[1]), "=r"((R)[2]), "=r"((R)[3]) : "r"(addr))

__device__ __forceinline__ void mma_bf16(float* c, const uint32_t* a, const uint32_t* b) {
    asm volatile("mma.sync.aligned.m16n8k16.row.col.f32.bf16.bf16.f32 "
        "{%0,%1,%2,%3}, {%4,%5,%6,%7}, {%8,%9}, {%0,%1,%2,%3};"
        : "+f"(c[0]), "+f"(c[1]), "+f"(c[2]), "+f"(c[3])
        : "r"(a[0]), "r"(a[1]), "r"(a[2]), "r"(a[3]), "r"(b[0]), "r"(b[1]));
}
#define CP_A16(dst, src) \
    asm volatile("cp.async.ca.shared.global [%0], [%1], 16;" :: "r"(dst), "l"(src))
#define CP_COMMIT()  asm volatile("cp.async.commit_group;")
#define CP_WAIT0()   asm volatile("cp.async.wait_group 0;")
#define CP_WAIT1()   asm volatile("cp.async.wait_group 1;")

__device__ __forceinline__ void split_bf(float v, uint16_t& h, uint16_t& l) {
    __nv_bfloat16 hb = __float2bfloat16(v);
    __nv_bfloat16 lb = __float2bfloat16(v - __bfloat162float(hb));
    h = __bfloat16_as_ushort(hb);
    l = __bfloat16_as_ushort(lb);
}

// ---------------- prep kernels ----------------
__global__ void detect64(const unsigned int* w, int* nz) {
    int t = blockIdx.x * blockDim.x + threadIdx.x;   // [0,4096)
    unsigned int bad = __ballot_sync(0xFFFFFFFFu, w[2 * t + 1] != 0u);
    if ((threadIdx.x & 31) == 0 && bad) atomicOr(nz, 1);
}
__global__ void tsplit_all(const float* __restrict__ w1, const float* __restrict__ wl,
                           const float* __restrict__ wr, const float* __restrict__ hw1,
                           const float* __restrict__ hw2, const float* __restrict__ hw3,
                           __nv_bfloat16* b1, __nv_bfloat16* b2, __nv_bfloat16* b3,
                           __nv_bfloat16* b4, __nv_bfloat16* b5) {
    int idx = blockIdx.x * blockDim.x + threadIdx.x;
    const float* W; __nv_bfloat16* bp; int K, N; int local;
    if (idx < 8192)        { local = idx;          W = w1;  bp = b1; K = 64;   N = 128; }
    else if (idx < 40960)  { local = idx - 8192;   W = nullptr; bp = b2; K = 256; N = 128; }
    else if (idx < 73728)  { local = idx - 40960;  W = hw1; bp = b3; K = 128;  N = 256; }
    else if (idx < 335872) { local = idx - 73728;  W = hw2; bp = b4; K = 256;  N = 1024; }
    else if (idx < 598016) { local = idx - 335872; W = hw3; bp = b5; K = 1024; N = 256; }
    else return;
    int n = local / K, k = local % K;
    float v;
    if (W) v = W[(size_t)k * N + n];
    else   v = (k < 128) ? wl[k * 128 + n] : wr[(k - 128) * 128 + n];
    uint16_t h, l;
    split_bf(v, h, l);
    size_t base = ((size_t)n * (K >> 5) + (k >> 5)) * 64 + (k & 31);
    bp[base] = __ushort_as_bfloat16(h);
    bp[base + 32] = __ushort_as_bfloat16(l);
}

// ---------------- edge scatter (8 edges per warp) ----------------
__global__ void edge_kernel(const void* __restrict__ ei, const float* __restrict__ h0,
                            float* __restrict__ sums, float* __restrict__ cnt,
                            const int* __restrict__ nz) {
    int warp0 = ((blockIdx.x * blockDim.x + threadIdx.x) >> 5) * 8;
    int lane = threadIdx.x & 31;
    const int is64 = (*nz == 0);
#pragma unroll
    for (int e = warp0; e < warp0 + 8; e++) {
        long long src, dst;
        if (is64) {
            const long long* p = (const long long*)ei;
            src = p[e]; dst = p[EE + e];
        } else {
            const int* p = (const int*)ei;
            src = p[e]; dst = p[EE + e];
        }
        float4 v = *(const float4*)(h0 + src * 128 + lane * 4);
        float* d = sums + dst * 128 + lane * 4;
        asm volatile("red.global.add.v4.f32 [%0], {%1, %2, %3, %4};"
                     :: "l"(d), "f"(v.x), "f"(v.y), "f"(v.z), "f"(v.w) : "memory");
        if (lane == 0) atomicAdd(cnt + dst, 1.0f);
    }
}

__global__ void fin_bn(const float* __restrict__ cs, const float* __restrict__ cq,
                       const float* __restrict__ gm, const float* __restrict__ bt,
                       float* __restrict__ sc, float* __restrict__ sh, int ncols) {
    int c = blockIdx.x * blockDim.x + threadIdx.x;
    if (c < ncols) {
        double mean = (double)cs[c] * (1.0 / (double)NN);
        double var  = (double)cq[c] * (1.0 / (double)NN) - mean * mean;
        if (var < 0.0) var = 0.0;
        float rstd = (float)(1.0 / sqrt(var + 1e-5));
        float s = gm[c] * rstd;
        sc[c] = s;
        sh[c] = bt[c] - (float)mean * s;
    }
}

// ---------------- pipelined mma.sync bf16x3 GEMM (BK=64, 512 threads) -------
// C[M,N] = T(A)[M,K] @ W + bias.  Bpk: packed split weights [N][K/32][hi32|lo32].
// MODE 0: plain | MODE 1: relu(a*sc+sh) | MODE 2: k<128: A(sums)/cnt; else aux(h0)
// CTA tile 128x128, BK=64, 16 warps (warp tile 32M x 32N). 1 barrier per chunk.
#define DSM_BYTES 131072
#define GTH 512

template<int MODE, int RELU, int STATS>
__global__ void __launch_bounds__(GTH, 1)
mgemm(const float* __restrict__ A, const __nv_bfloat16* __restrict__ Bpk,
      const float* __restrict__ bias, float* __restrict__ C,
      int M, int K, int N,
      const float* __restrict__ sc, const float* __restrict__ sh,
      const float* __restrict__ aux, const float* __restrict__ cnt,
      float* __restrict__ gs, float* __restrict__ gq) {
    extern __shared__ __align__(16) char dsm[];
    char* sAc = dsm;
    const uint32_t sA_b = smem_u32(dsm);
    const uint32_t sB_b = sA_b + 65536;

    const int tid = threadIdx.x, lane = tid & 31, wid = tid >> 5;
    const int wm = (wid & 3) * 32, wn = (wid >> 2) * 32;
    const int m0 = blockIdx.y * 128, n0 = blockIdx.x * 128;
    const int nch = K >> 6;
    const int kc32 = K >> 5;

    float acc[2][4][4];
#pragma unroll
    for (int i = 0; i < 2; i++)
#pragma unroll
        for (int j = 0; j < 4; j++)
#pragma unroll
            for (int q = 0; q < 4; q++) acc[i][j][q] = 0.f;

    auto issueB = [&](int c) {
        const int buf = c & 1;
        const uint32_t bb = sB_b + buf * 32768;
#pragma unroll
        for (int l = 0; l < 4; l++) {
            int pos = tid + l * GTH;
            int row = pos >> 4, q = pos & 15;
            const char* srcB = (const char*)(Bpk + ((size_t)(n0 + row) * kc32 + 2 * c) * 64) + q * 16;
            uint32_t dst = bb + row * 256 + (uint32_t)((q >> 3) * 128)
                         + (((uint32_t)((q & 7) * 16)) ^ (uint32_t)((row & 7) * 16));
            CP_A16(dst, srcB);
        }
        CP_COMMIT();
    };

    auto load_A = [&](int c, float4* rv) {
        const int k0 = c << 6;
#pragma unroll
        for (int l = 0; l < 4; l++) {
            int pos = tid + l * GTH;
            int row = pos >> 4, q = pos & 15;
            int grow = m0 + row;
            float4 v = make_float4(0.f, 0.f, 0.f, 0.f);
            if (grow < M) {
                if (MODE == 2) {
                    if (k0 < 128) v = *(const float4*)(A + (size_t)grow * 128 + k0 + q * 4);
                    else          v = *(const float4*)(aux + (size_t)grow * 128 + (k0 - 128) + q * 4);
                } else {
                    v = *(const float4*)(A + (size_t)grow * K + k0 + q * 4);
                }
            }
            rv[l] = v;
        }
    };
    // (row, q) quad covers k = q*4..q*4+3 -> group (q>>3), in-group byte (q&7)*8
    auto split_store = [&](int c, float4* rv) {
        const int buf = c & 1;
        const int k0 = c << 6;
        char* sAd = sAc + buf * 32768;
#pragma unroll
        for (int l = 0; l < 4; l++) {
            int pos = tid + l * GTH;
            int row = pos >> 4, q = pos & 15;
            int grow = m0 + row;
            float4 v = rv[l];
            if (MODE == 1) {
                float4 s4 = *(const float4*)(sc + k0 + q * 4);
                float4 h4 = *(const float4*)(sh + k0 + q * 4);
                v.x = fmaxf(fmaf(v.x, s4.x, h4.x), 0.f);
                v.y = fmaxf(fmaf(v.y, s4.y, h4.y), 0.f);
                v.z = fmaxf(fmaf(v.z, s4.z, h4.z), 0.f);
                v.w = fmaxf(fmaf(v.w, s4.w, h4.w), 0.f);
            }
            if (MODE == 2 && k0 < 128) {
                float cv = (grow < M) ? cnt[grow] : 1.f;
                float ic = 1.f / fmaxf(cv, 1.f);
                v.x *= ic; v.y *= ic; v.z *= ic; v.w *= ic;
            }
            uint16_t hx, hy, hz, hw_, lx, ly, lz, lw;
            split_bf(v.x, hx, lx); split_bf(v.y, hy, ly);
            split_bf(v.z, hz, lz); split_bf(v.w, hw_, lw);
            uint2 hi2 = make_uint2((uint32_t)hx | ((uint32_t)hy << 16),
                                   (uint32_t)hz | ((uint32_t)hw_ << 16));
            uint2 lo2 = make_uint2((uint32_t)lx | ((uint32_t)ly << 16),
                                   (uint32_t)lz | ((uint32_t)lw << 16));
            uint32_t xr = (uint32_t)((row & 7) * 16);
            uint32_t base = (uint32_t)(row * 256 + (q >> 3) * 128);
            uint32_t qq = (uint32_t)((q & 7) * 8);
            *(uint2*)(sAd + base + (qq ^ xr)) = hi2;
            *(uint2*)(sAd + base + ((64 + qq) ^ xr)) = lo2;
        }
    };

    // ---- prologue ----
    issueB(0);
    if (nch > 1) issueB(1);
    {
        float4 rv0[4];
        load_A(0, rv0);
        split_store(0, rv0);
    }
    if (nch > 1) CP_WAIT1(); else CP_WAIT0();
    __syncthreads();

    // ---- mainloop: one barrier per 64-k chunk ----
    for (int c = 0; c < nch; c++) {
        const int buf = c & 1;
        float4 rv[4];
        if (c + 1 < nch) load_A(c + 1, rv);
        const uint32_t ab = sA_b + buf * 32768;
        const uint32_t bb = sB_b + buf * 32768;
#pragma unroll
        for (int ks = 0; ks < 4; ks++) {
            const uint32_t gb = (uint32_t)((ks >> 1) * 128);
            const uint32_t kb = (uint32_t)((ks & 1) * 32);
            uint32_t afh[2][4], afl[2][4];
#pragma unroll
            for (int mt = 0; mt < 2; mt++) {
                int row = wm + mt * 16 + (lane & 15);
                uint32_t cb = kb + (uint32_t)((lane >> 4) * 16);
                uint32_t x = (uint32_t)((row & 7) * 16);
                uint32_t rb = ab + row * 256 + gb;
                LDSM4(afh[mt], rb + (cb ^ x));
                LDSM4(afl[mt], rb + ((cb + 64) ^ x));
            }
            uint32_t bfh[2][4], bfl[2][4];
#pragma unroll
            for (int np = 0; np < 2; np++) {
                int row = wn + np * 16 + (lane & 7) + ((lane >> 4) & 1) * 8;
                uint32_t cb = kb + (uint32_t)(((lane >> 3) & 1) * 16);
                uint32_t x = (uint32_t)((row & 7) * 16);
                uint32_t rb = bb + row * 256 + gb;
                LDSM4(bfh[np], rb + (cb ^ x));
                LDSM4(bfl[np], rb + ((cb + 64) ^ x));
            }
#pragma unroll
            for (int mt = 0; mt < 2; mt++)
#pragma unroll
                for (int np = 0; np < 2; np++)
#pragma unroll
                    for (int sub = 0; sub < 2; sub++) {
                        int nt = np * 2 + sub;
                        mma_bf16(acc[mt][nt], afh[mt], &bfh[np][sub * 2]);
                        mma_bf16(acc[mt][nt], afl[mt], &bfh[np][sub * 2]);
                        mma_bf16(acc[mt][nt], afh[mt], &bfl[np][sub * 2]);
                    }
        }
        if (c + 1 < nch) {
            split_store(c + 1, rv);
            CP_WAIT0();
        }
        __syncthreads();
        if (c + 2 < nch) issueB(c + 2);
    }

    // ---- epilogue ----
    float* ssum = (float*)dsm;
    if (STATS) {
        if (tid < 256) ssum[tid] = 0.f;
        __syncthreads();
    }
#pragma unroll
    for (int mt = 0; mt < 2; mt++) {
        int row = m0 + wm + mt * 16 + (lane >> 2);
#pragma unroll
        for (int nt = 0; nt < 4; nt++) {
            int col = n0 + wn + nt * 8 + (lane & 3) * 2;
            float b0 = bias[col], b1 = bias[col + 1];
            float2 o0 = make_float2(acc[mt][nt][0] + b0, acc[mt][nt][1] + b1);
            float2 o1 = make_float2(acc[mt][nt][2] + b0, acc[mt][nt][3] + b1);
            if (RELU) {
                o0.x = fmaxf(o0.x, 0.f); o0.y = fmaxf(o0.y, 0.f);
                o1.x = fmaxf(o1.x, 0.f); o1.y = fmaxf(o1.y, 0.f);
            }
            if (row < M)     *(float2*)(C + (size_t)row * N + col) = o0;
            if (row + 8 < M) *(float2*)(C + (size_t)(row + 8) * N + col) = o1;
        }
    }
    if (STATS) {
#pragma unroll
        for (int nt = 0; nt < 4; nt++) {
            int colr = wn + nt * 8 + (lane & 3) * 2;
            float b0 = bias[n0 + colr], b1 = bias[n0 + colr + 1];
            float s0 = 0.f, s1 = 0.f, q0 = 0.f, q1 = 0.f;
#pragma unroll
            for (int mt = 0; mt < 2; mt++) {
                int r = m0 + wm + mt * 16 + (lane >> 2);
                float ok0 = (r < M) ? 1.f : 0.f;
                float ok1 = (r + 8 < M) ? 1.f : 0.f;
                float v00 = (acc[mt][nt][0] + b0) * ok0;
                float v01 = (acc[mt][nt][1] + b1) * ok0;
                float v10 = (acc[mt][nt][2] + b0) * ok1;
                float v11 = (acc[mt][nt][3] + b1) * ok1;
                s0 += v00 + v10; s1 += v01 + v11;
                q0 += v00 * v00 + v10 * v10;
                q1 += v01 * v01 + v11 * v11;
            }
#pragma unroll
            for (int d = 4; d < 32; d <<= 1) {
                s0 += __shfl_xor_sync(0xFFFFFFFFu, s0, d);
                s1 += __shfl_xor_sync(0xFFFFFFFFu, s1, d);
                q0 += __shfl_xor_sync(0xFFFFFFFFu, q0, d);
                q1 += __shfl_xor_sync(0xFFFFFFFFu, q1, d);
            }
            if (lane < 4) {
                atomicAdd(&ssum[colr], s0);
                atomicAdd(&ssum[colr + 1], s1);
                atomicAdd(&ssum[128 + colr], q0);
                atomicAdd(&ssum[128 + colr + 1], q1);
            }
        }
        __syncthreads();
        if (tid < 128)       atomicAdd(&gs[n0 + tid], ssum[tid]);
        else if (tid < 256)  atomicAdd(&gq[n0 + tid - 128], ssum[tid]);
    }
}

// ---------------- final layer ----------------
__global__ __launch_bounds__(256)
void final_kernel(const float* __restrict__ g3,
                  const float* __restrict__ sc, const float* __restrict__ sh,
                  const float* __restrict__ hw4, const float* __restrict__ hb4,
                  float* __restrict__ pen, float* __restrict__ logits) {
    __shared__ float w4s[256 * 16];
    __shared__ float at[16 * 256];
    int t = threadIdx.x;
    for (int i = t; i < 4096; i += 256) w4s[i] = hw4[i];
    long long r0 = (long long)blockIdx.x * 16;
#pragma unroll
    for (int i = 0; i < 16; i++) {
        float v = g3[(r0 + i) * 256 + t];
        v = fmaxf(fmaf(v, sc[t], sh[t]), 0.f);
        at[i * 256 + t] = v;
        pen[(r0 + i) * 256 + t] = v;
    }
    __syncthreads();
    int r = t >> 4, c = t & 15;
    float acc = hb4[c];
#pragma unroll 8
    for (int k = 0; k < 256; k++)
        acc = fmaf(at[r * 256 + k], w4s[k * 16 + c], acc);
    logits[(r0 + r) * 16 + c] = acc;
}

// ---------------- launch ----------------
extern "C" void kernel_launch(void* const* d_in, const int* in_sizes, int n_in,
                              void* d_out, int out_size) {
    const float* x   = (const float*)d_in[0];
    const void*  ei  = d_in[1];
    const float* w1  = (const float*)d_in[2];
    const float* b1  = (const float*)d_in[3];
    const float* wl  = (const float*)d_in[4];
    const float* bl  = (const float*)d_in[5];
    const float* wr  = (const float*)d_in[6];
    const float* hw1 = (const float*)d_in[7];
    const float* hb1 = (const float*)d_in[8];
    const float* ga1 = (const float*)d_in[9];
    const float* be1 = (const float*)d_in[10];
    const float* hw2 = (const float*)d_in[11];
    const float* hb2 = (const float*)d_in[12];
    const float* ga2 = (const float*)d_in[13];
    const float* be2 = (const float*)d_in[14];
    const float* hw3 = (const float*)d_in[15];
    const float* hb3 = (const float*)d_in[16];
    const float* ga3 = (const float*)d_in[17];
    const float* be3 = (const float*)d_in[18];
    const float* hw4 = (const float*)d_in[19];
    const float* hb4 = (const float*)d_in[20];

    float* out_logits = (float*)d_out;
    float* out_pen    = (float*)d_out + (size_t)NN * 16;
    float* out_feat   = (float*)d_out + (size_t)NN * (16 + 256);

    float *h0, *sums, *cnt, *p1, *p2, *p3, *sc, *sh, *cs, *cq;
    __nv_bfloat16 *b1p, *b2p, *b3p, *b4p, *b5p;
    int* nz;
    cudaGetSymbolAddress((void**)&h0,   g_h0);
    cudaGetSymbolAddress((void**)&sums, g_sums);
    cudaGetSymbolAddress((void**)&cnt,  g_cnt);
    cudaGetSymbolAddress((void**)&p1,   g_p1);
    cudaGetSymbolAddress((void**)&p2,   g_p2);
    cudaGetSymbolAddress((void**)&p3,   g_p3);
    cudaGetSymbolAddress((void**)&sc,   g_scale);
    cudaGetSymbolAddress((void**)&sh,   g_shift);
    cudaGetSymbolAddress((void**)&cs,   g_cs);
    cudaGetSymbolAddress((void**)&cq,   g_cq);
    cudaGetSymbolAddress((void**)&nz,   g_nz);
    cudaGetSymbolAddress((void**)&b1p, g_b1);
    cudaGetSymbolAddress((void**)&b2p, g_b2);
    cudaGetSymbolAddress((void**)&b3p, g_b3);
    cudaGetSymbolAddress((void**)&b4p, g_b4);
    cudaGetSymbolAddress((void**)&b5p, g_b5);

    const int M = NN;
    const int MT = (M + 127) / 128;   // 782
    dim3 blk(256);
    dim3 gblk(GTH);

    cudaFuncSetAttribute(mgemm<0,1,0>, cudaFuncAttributeMaxDynamicSharedMemorySize, DSM_BYTES);
    cudaFuncSetAttribute(mgemm<2,0,0>, cudaFuncAttributeMaxDynamicSharedMemorySize, DSM_BYTES);
    cudaFuncSetAttribute(mgemm<0,0,1>, cudaFuncAttributeMaxDynamicSharedMemorySize, DSM_BYTES);
    cudaFuncSetAttribute(mgemm<1,0,1>, cudaFuncAttributeMaxDynamicSharedMemorySize, DSM_BYTES);

    // zeroing via memset DMA (graph-capturable memset nodes, no SM work)
    cudaMemsetAsync(sums, 0, (size_t)NN * 128 * sizeof(float));
    cudaMemsetAsync(cnt,  0, (size_t)NN * sizeof(float));
    cudaMemsetAsync(cs,   0, 1536 * sizeof(float));
    cudaMemsetAsync(cq,   0, 1536 * sizeof(float));
    cudaMemsetAsync(nz,   0, sizeof(int));

    // 0: dtype detection
    detect64<<<16, blk>>>((const unsigned int*)ei, nz);
    // 1: all weight packs
    tsplit_all<<<(598016 + 255) / 256, blk>>>(w1, wl, wr, hw1, hw2, hw3,
                                              b1p, b2p, b3p, b4p, b5p);
    // 2: G1
    mgemm<0,1,0><<<dim3(1, MT), gblk, DSM_BYTES>>>(x, b1p, b1, h0, M, 64, 128,
        nullptr, nullptr, nullptr, nullptr, nullptr, nullptr);
    // 3: edge scatter
    edge_kernel<<<EE / 64, blk>>>(ei, h0, sums, cnt, nz);
    // 4: G2
    mgemm<2,0,0><<<dim3(1, MT), gblk, DSM_BYTES>>>(sums, b2p, bl, out_feat, M, 256, 128,
        nullptr, nullptr, h0, cnt, nullptr, nullptr);
    // 5: G3 (+stats slice 0)
    mgemm<0,0,1><<<dim3(2, MT), gblk, DSM_BYTES>>>(out_feat, b3p, hb1, p1, M, 128, 256,
        nullptr, nullptr, nullptr, nullptr, cs, cq);
    // 6
    fin_bn<<<1, 256>>>(cs, cq, ga1, be1, sc, sh, 256);
    // 7: G4 (+stats slice 1)
    mgemm<1,0,1><<<dim3(8, MT), gblk, DSM_BYTES>>>(p1, b4p, hb2, p2, M, 256, 1024,
        sc, sh, nullptr, nullptr, cs + 256, cq + 256);
    // 8
    fin_bn<<<4, 256>>>(cs + 256, cq + 256, ga2, be2, sc, sh, 1024);
    // 9: G5 (+stats slice 2)
    mgemm<1,0,1><<<dim3(2, MT), gblk, DSM_BYTES>>>(p2, b5p, hb3, p3, M, 1024, 256,
        sc, sh, nullptr, nullptr, cs + 1280, cq + 1280);
    // 10
    fin_bn<<<1, 256>>>(cs + 1280, cq + 1280, ga3, be3, sc, sh, 256);
    // 11: final
    final_kernel<<<NN / 16, blk>>>(p3, sc, sh, hw4, hb4, out_pen, out_logits);
}

// round 14
// speedup vs baseline: 1.2779x; 1.1827x over previous
#include <cuda_runtime.h>
#include <cuda_fp16.h>
#include <cstdint>

// ---------------- problem constants ----------------
#define NN 100000
#define EE 1600000

// ---------------- scratch (device globals) ----------------
__device__ float  g_h0[(size_t)NN * 128];
__device__ float  g_sums[(size_t)NN * 128];
__device__ float  g_cnt[NN];
__device__ float  g_p1[(size_t)NN * 256];
__device__ float  g_p2[(size_t)NN * 1024];
__device__ float  g_p3[(size_t)NN * 256];
__device__ float  g_cs[1536];      // stats slices: L1 @0(256), L2 @256(1024), L3 @1280(256)
__device__ float  g_cq[1536];
__device__ float  g_scale[1024];
__device__ float  g_shift[1024];
__device__ int    g_nz;            // nonzero high words -> edges are int32
// packed fp16 weights, [N][K] row-major
__device__ __half g_b1[128 * 64];
__device__ __half g_b2[128 * 256];
__device__ __half g_b3[256 * 128];
__device__ __half g_b4[1024 * 256];
__device__ __half g_b5[256 * 1024];

// ---------------- helpers ----------------
__device__ __forceinline__ uint32_t smem_u32(const void* p) {
    uint32_t a;
    asm("{ .reg .u64 t; cvta.to.shared.u64 t, %1; cvt.u32.u64 %0, t; }" : "=r"(a) : "l"(p));
    return a;
}
#define LDSM4(R, addr) \
    asm volatile("ldmatrix.sync.aligned.m8n8.x4.shared.b16 {%0,%1,%2,%3}, [%4];" \
        : "=r"((R)[0]), "=r"((R)[1]), "=r"((R)[2]), "=r"((R)[3]) : "r"(addr))

__device__ __forceinline__ void mma_f16(float* c, const uint32_t* a, const uint32_t* b) {
    asm volatile("mma.sync.aligned.m16n8k16.row.col.f32.f16.f16.f32 "
        "{%0,%1,%2,%3}, {%4,%5,%6,%7}, {%8,%9}, {%0,%1,%2,%3};"
        : "+f"(c[0]), "+f"(c[1]), "+f"(c[2]), "+f"(c[3])
        : "r"(a[0]), "r"(a[1]), "r"(a[2]), "r"(a[3]), "r"(b[0]), "r"(b[1]));
}
#define CP_A16(dst, src) \
    asm volatile("cp.async.ca.shared.global [%0], [%1], 16;" :: "r"(dst), "l"(src))
#define CP_COMMIT()  asm volatile("cp.async.commit_group;")
#define CP_WAIT0()   asm volatile("cp.async.wait_group 0;")
#define CP_WAIT1()   asm volatile("cp.async.wait_group 1;")

__device__ __forceinline__ void split_h(float v, uint16_t& h, uint16_t& l) {
    __half hh = __float2half_rn(v);
    __half ll = __float2half_rn(v - __half2float(hh));
    h = __half_as_ushort(hh);
    l = __half_as_ushort(ll);
}

// ---------------- prep kernels ----------------
// zero_all: sums (NN*128), cnt (NN), cs/cq (2x1536), nz
__global__ void zero_all(float* sums, float* cnt, float* cs, float* cq, int* nz) {
    int i = (blockIdx.x * blockDim.x + threadIdx.x) * 4;
    const int n_sums = NN * 128;
    if (i < n_sums) {
        *(float4*)(sums + i) = make_float4(0.f, 0.f, 0.f, 0.f);
    } else {
        int j = i - n_sums;
        if (j < NN) {
            for (int q = 0; q < 4 && j + q < NN; q++) cnt[j + q] = 0.f;
        } else {
            int s = j - NN;
            if (s < 1536) { *(float4*)(cs + s) = make_float4(0.f, 0.f, 0.f, 0.f);
                            *(float4*)(cq + s) = make_float4(0.f, 0.f, 0.f, 0.f); }
            if (s == 0) *nz = 0;
        }
    }
}
__global__ void detect64(const unsigned int* w, int* nz) {
    int t = blockIdx.x * blockDim.x + threadIdx.x;   // [0,4096)
    unsigned int bad = __ballot_sync(0xFFFFFFFFu, w[2 * t + 1] != 0u);
    if ((threadIdx.x & 31) == 0 && bad) atomicOr(nz, 1);
}
// all 5 weight packs, transposed to [N][K] fp16
__global__ void tsplit_all(const float* __restrict__ w1, const float* __restrict__ wl,
                           const float* __restrict__ wr, const float* __restrict__ hw1,
                           const float* __restrict__ hw2, const float* __restrict__ hw3,
                           __half* b1, __half* b2, __half* b3, __half* b4, __half* b5) {
    int idx = blockIdx.x * blockDim.x + threadIdx.x;
    const float* W; __half* bp; int K, N; int local;
    if (idx < 8192)        { local = idx;          W = w1;  bp = b1; K = 64;   N = 128; }
    else if (idx < 40960)  { local = idx - 8192;   W = nullptr; bp = b2; K = 256; N = 128; }
    else if (idx < 73728)  { local = idx - 40960;  W = hw1; bp = b3; K = 128;  N = 256; }
    else if (idx < 335872) { local = idx - 73728;  W = hw2; bp = b4; K = 256;  N = 1024; }
    else if (idx < 598016) { local = idx - 335872; W = hw3; bp = b5; K = 1024; N = 256; }
    else return;
    int n = local / K, k = local % K;
    float v;
    if (W) v = W[(size_t)k * N + n];
    else   v = (k < 128) ? wl[k * 128 + n] : wr[(k - 128) * 128 + n];
    bp[(size_t)n * K + k] = __float2half_rn(v);
}

// ---------------- edge scatter (8 edges per warp) ----------------
__global__ void edge_kernel(const void* __restrict__ ei, const float* __restrict__ h0,
                            float* __restrict__ sums, float* __restrict__ cnt,
                            const int* __restrict__ nz) {
    int warp0 = ((blockIdx.x * blockDim.x + threadIdx.x) >> 5) * 8;
    int lane = threadIdx.x & 31;
    const int is64 = (*nz == 0);
#pragma unroll
    for (int e = warp0; e < warp0 + 8; e++) {
        long long src, dst;
        if (is64) {
            const long long* p = (const long long*)ei;
            src = p[e]; dst = p[EE + e];
        } else {
            const int* p = (const int*)ei;
            src = p[e]; dst = p[EE + e];
        }
        float4 v = *(const float4*)(h0 + src * 128 + lane * 4);
        float* d = sums + dst * 128 + lane * 4;
        asm volatile("red.global.add.v4.f32 [%0], {%1, %2, %3, %4};"
                     :: "l"(d), "f"(v.x), "f"(v.y), "f"(v.z), "f"(v.w) : "memory");
        if (lane == 0) atomicAdd(cnt + dst, 1.0f);
    }
}

__global__ void fin_bn(const float* __restrict__ cs, const float* __restrict__ cq,
                       const float* __restrict__ gm, const float* __restrict__ bt,
                       float* __restrict__ sc, float* __restrict__ sh, int ncols) {
    int c = blockIdx.x * blockDim.x + threadIdx.x;
    if (c < ncols) {
        double mean = (double)cs[c] * (1.0 / (double)NN);
        double var  = (double)cq[c] * (1.0 / (double)NN) - mean * mean;
        if (var < 0.0) var = 0.0;
        float rstd = (float)(1.0 / sqrt(var + 1e-5));
        float s = gm[c] * rstd;
        sc[c] = s;
        sh[c] = bt[c] - (float)mean * s;
    }
}

// ---------------- pipelined mma.sync fp16x2 GEMM (BK=64, 512 threads) -------
// C[M,N] = T(A)[M,K] @ W + bias.  A split fp16 hi/lo; B single fp16 [N][K].
// MODE 0: plain | MODE 1: relu(a*sc+sh) | MODE 2: k<128: A(sums)/cnt; else aux(h0)
// CTA tile 128x128, BK=64, 16 warps (warp tile 32M x 32N). 1 barrier per chunk.
// smem: sA 2 x (128 rows x 256B) = 64KB;  sB 2 x (128 rows x 128B) = 32KB
#define DSM_BYTES 98304
#define GTH 512

template<int MODE, int RELU, int STATS>
__global__ void __launch_bounds__(GTH, 1)
mgemm(const float* __restrict__ A, const __half* __restrict__ Bpk,
      const float* __restrict__ bias, float* __restrict__ C,
      int M, int K, int N,
      const float* __restrict__ sc, const float* __restrict__ sh,
      const float* __restrict__ aux, const float* __restrict__ cnt,
      float* __restrict__ gs, float* __restrict__ gq) {
    extern __shared__ __align__(16) char dsm[];
    char* sAc = dsm;
    const uint32_t sA_b = smem_u32(dsm);
    const uint32_t sB_b = sA_b + 65536;

    const int tid = threadIdx.x, lane = tid & 31, wid = tid >> 5;
    const int wm = (wid & 3) * 32, wn = (wid >> 2) * 32;
    const int m0 = blockIdx.y * 128, n0 = blockIdx.x * 128;
    const int nch = K >> 6;

    float acc[2][4][4];
#pragma unroll
    for (int i = 0; i < 2; i++)
#pragma unroll
        for (int j = 0; j < 4; j++)
#pragma unroll
            for (int q = 0; q < 4; q++) acc[i][j][q] = 0.f;

    // ---- B chunk c: 128 rows x 64 fp16 = 128B/row, swizzled ----
    auto issueB = [&](int c) {
        const int buf = c & 1;
        const uint32_t bb = sB_b + buf * 16384;
#pragma unroll
        for (int l = 0; l < 2; l++) {
            int pos = tid + l * GTH;
            int row = pos >> 3, q = pos & 7;
            const char* srcB = (const char*)(Bpk + (size_t)(n0 + row) * K + c * 64) + q * 16;
            uint32_t dst = bb + row * 128 + (((uint32_t)(q * 16)) ^ (uint32_t)((row & 7) * 16));
            CP_A16(dst, srcB);
        }
        CP_COMMIT();
    };

    auto load_A = [&](int c, float4* rv) {
        const int k0 = c << 6;
#pragma unroll
        for (int l = 0; l < 4; l++) {
            int pos = tid + l * GTH;
            int row = pos >> 4, q = pos & 15;
            int grow = m0 + row;
            float4 v = make_float4(0.f, 0.f, 0.f, 0.f);
            if (grow < M) {
                if (MODE == 2) {
                    if (k0 < 128) v = *(const float4*)(A + (size_t)grow * 128 + k0 + q * 4);
                    else          v = *(const float4*)(aux + (size_t)grow * 128 + (k0 - 128) + q * 4);
                } else {
                    v = *(const float4*)(A + (size_t)grow * K + k0 + q * 4);
                }
            }
            rv[l] = v;
        }
    };
    // A row 256B: group (q>>3)*128; hi at +0..63, lo at +64..127; in-group byte (q&7)*8
    auto split_store = [&](int c, float4* rv) {
        const int buf = c & 1;
        const int k0 = c << 6;
        char* sAd = sAc + buf * 32768;
#pragma unroll
        for (int l = 0; l < 4; l++) {
            int pos = tid + l * GTH;
            int row = pos >> 4, q = pos & 15;
            int grow = m0 + row;
            float4 v = rv[l];
            if (MODE == 1) {
                float4 s4 = *(const float4*)(sc + k0 + q * 4);
                float4 h4 = *(const float4*)(sh + k0 + q * 4);
                v.x = fmaxf(fmaf(v.x, s4.x, h4.x), 0.f);
                v.y = fmaxf(fmaf(v.y, s4.y, h4.y), 0.f);
                v.z = fmaxf(fmaf(v.z, s4.z, h4.z), 0.f);
                v.w = fmaxf(fmaf(v.w, s4.w, h4.w), 0.f);
            }
            if (MODE == 2 && k0 < 128) {
                float cv = (grow < M) ? cnt[grow] : 1.f;
                float ic = 1.f / fmaxf(cv, 1.f);
                v.x *= ic; v.y *= ic; v.z *= ic; v.w *= ic;
            }
            uint16_t hx, hy, hz, hw_, lx, ly, lz, lw;
            split_h(v.x, hx, lx); split_h(v.y, hy, ly);
            split_h(v.z, hz, lz); split_h(v.w, hw_, lw);
            uint2 hi2 = make_uint2((uint32_t)hx | ((uint32_t)hy << 16),
                                   (uint32_t)hz | ((uint32_t)hw_ << 16));
            uint2 lo2 = make_uint2((uint32_t)lx | ((uint32_t)ly << 16),
                                   (uint32_t)lz | ((uint32_t)lw << 16));
            uint32_t xr = (uint32_t)((row & 7) * 16);
            uint32_t base = (uint32_t)(row * 256 + (q >> 3) * 128);
            uint32_t qq = (uint32_t)((q & 7) * 8);
            *(uint2*)(sAd + base + (qq ^ xr)) = hi2;
            *(uint2*)(sAd + base + ((64 + qq) ^ xr)) = lo2;
        }
    };

    // ---- prologue ----
    issueB(0);
    if (nch > 1) issueB(1);
    {
        float4 rv0[4];
        load_A(0, rv0);
        split_store(0, rv0);
    }
    if (nch > 1) CP_WAIT1(); else CP_WAIT0();
    __syncthreads();

    // ---- mainloop: one barrier per 64-k chunk ----
    for (int c = 0; c < nch; c++) {
        const int buf = c & 1;
        float4 rv[4];
        if (c + 1 < nch) load_A(c + 1, rv);
        const uint32_t ab = sA_b + buf * 32768;
        const uint32_t bb = sB_b + buf * 16384;
#pragma unroll
        for (int ks = 0; ks < 4; ks++) {
            const uint32_t gb = (uint32_t)((ks >> 1) * 128);
            const uint32_t kb = (uint32_t)((ks & 1) * 32);
            uint32_t afh[2][4], afl[2][4];
#pragma unroll
            for (int mt = 0; mt < 2; mt++) {
                int row = wm + mt * 16 + (lane & 15);
                uint32_t cb = kb + (uint32_t)((lane >> 4) * 16);
                uint32_t x = (uint32_t)((row & 7) * 16);
                uint32_t rb = ab + row * 256 + gb;
                LDSM4(afh[mt], rb + (cb ^ x));
                LDSM4(afl[mt], rb + ((cb + 64) ^ x));
            }
            uint32_t bf[2][4];
#pragma unroll
            for (int np = 0; np < 2; np++) {
                int row = wn + np * 16 + (lane & 7) + ((lane >> 4) & 1) * 8;
                uint32_t cb = (uint32_t)(ks * 32) + (uint32_t)(((lane >> 3) & 1) * 16);
                uint32_t x = (uint32_t)((row & 7) * 16);
                LDSM4(bf[np], bb + row * 128 + (cb ^ x));
            }
#pragma unroll
            for (int mt = 0; mt < 2; mt++)
#pragma unroll
                for (int np = 0; np < 2; np++)
#pragma unroll
                    for (int sub = 0; sub < 2; sub++) {
                        int nt = np * 2 + sub;
                        mma_f16(acc[mt][nt], afh[mt], &bf[np][sub * 2]);
                        mma_f16(acc[mt][nt], afl[mt], &bf[np][sub * 2]);
                    }
        }
        if (c + 1 < nch) {
            split_store(c + 1, rv);
            CP_WAIT0();
        }
        __syncthreads();
        if (c + 2 < nch) issueB(c + 2);
    }

    // ---- epilogue ----
    float* ssum = (float*)dsm;
    if (STATS) {
        if (tid < 256) ssum[tid] = 0.f;
        __syncthreads();
    }
#pragma unroll
    for (int mt = 0; mt < 2; mt++) {
        int row = m0 + wm + mt * 16 + (lane >> 2);
#pragma unroll
        for (int nt = 0; nt < 4; nt++) {
            int col = n0 + wn + nt * 8 + (lane & 3) * 2;
            float b0 = bias[col], b1 = bias[col + 1];
            float2 o0 = make_float2(acc[mt][nt][0] + b0, acc[mt][nt][1] + b1);
            float2 o1 = make_float2(acc[mt][nt][2] + b0, acc[mt][nt][3] + b1);
            if (RELU) {
                o0.x = fmaxf(o0.x, 0.f); o0.y = fmaxf(o0.y, 0.f);
                o1.x = fmaxf(o1.x, 0.f); o1.y = fmaxf(o1.y, 0.f);
            }
            if (row < M)     *(float2*)(C + (size_t)row * N + col) = o0;
            if (row + 8 < M) *(float2*)(C + (size_t)(row + 8) * N + col) = o1;
        }
    }
    if (STATS) {
#pragma unroll
        for (int nt = 0; nt < 4; nt++) {
            int colr = wn + nt * 8 + (lane & 3) * 2;
            float b0 = bias[n0 + colr], b1 = bias[n0 + colr + 1];
            float s0 = 0.f, s1 = 0.f, q0 = 0.f, q1 = 0.f;
#pragma unroll
            for (int mt = 0; mt < 2; mt++) {
                int r = m0 + wm + mt * 16 + (lane >> 2);
                float ok0 = (r < M) ? 1.f : 0.f;
                float ok1 = (r + 8 < M) ? 1.f : 0.f;
                float v00 = (acc[mt][nt][0] + b0) * ok0;
                float v01 = (acc[mt][nt][1] + b1) * ok0;
                float v10 = (acc[mt][nt][2] + b0) * ok1;
                float v11 = (acc[mt][nt][3] + b1) * ok1;
                s0 += v00 + v10; s1 += v01 + v11;
                q0 += v00 * v00 + v10 * v10;
                q1 += v01 * v01 + v11 * v11;
            }
#pragma unroll
            for (int d = 4; d < 32; d <<= 1) {
                s0 += __shfl_xor_sync(0xFFFFFFFFu, s0, d);
                s1 += __shfl_xor_sync(0xFFFFFFFFu, s1, d);
                q0 += __shfl_xor_sync(0xFFFFFFFFu, q0, d);
                q1 += __shfl_xor_sync(0xFFFFFFFFu, q1, d);
            }
            if (lane < 4) {
                atomicAdd(&ssum[colr], s0);
                atomicAdd(&ssum[colr + 1], s1);
                atomicAdd(&ssum[128 + colr], q0);
                atomicAdd(&ssum[128 + colr + 1], q1);
            }
        }
        __syncthreads();
        if (tid < 128)       atomicAdd(&gs[n0 + tid], ssum[tid]);
        else if (tid < 256)  atomicAdd(&gq[n0 + tid - 128], ssum[tid]);
    }
}

// ---------------- final layer ----------------
__global__ __launch_bounds__(256)
void final_kernel(const float* __restrict__ g3,
                  const float* __restrict__ sc, const float* __restrict__ sh,
                  const float* __restrict__ hw4, const float* __restrict__ hb4,
                  float* __restrict__ pen, float* __restrict__ logits) {
    __shared__ float w4s[256 * 16];
    __shared__ float at[16 * 256];
    int t = threadIdx.x;
    for (int i = t; i < 4096; i += 256) w4s[i] = hw4[i];
    long long r0 = (long long)blockIdx.x * 16;
#pragma unroll
    for (int i = 0; i < 16; i++) {
        float v = g3[(r0 + i) * 256 + t];
        v = fmaxf(fmaf(v, sc[t], sh[t]), 0.f);
        at[i * 256 + t] = v;
        pen[(r0 + i) * 256 + t] = v;
    }
    __syncthreads();
    int r = t >> 4, c = t & 15;
    float acc = hb4[c];
#pragma unroll 8
    for (int k = 0; k < 256; k++)
        acc = fmaf(at[r * 256 + k], w4s[k * 16 + c], acc);
    logits[(r0 + r) * 16 + c] = acc;
}

// ---------------- launch ----------------
extern "C" void kernel_launch(void* const* d_in, const int* in_sizes, int n_in,
                              void* d_out, int out_size) {
    const float* x   = (const float*)d_in[0];
    const void*  ei  = d_in[1];
    const float* w1  = (const float*)d_in[2];
    const float* b1  = (const float*)d_in[3];
    const float* wl  = (const float*)d_in[4];
    const float* bl  = (const float*)d_in[5];
    const float* wr  = (const float*)d_in[6];
    const float* hw1 = (const float*)d_in[7];
    const float* hb1 = (const float*)d_in[8];
    const float* ga1 = (const float*)d_in[9];
    const float* be1 = (const float*)d_in[10];
    const float* hw2 = (const float*)d_in[11];
    const float* hb2 = (const float*)d_in[12];
    const float* ga2 = (const float*)d_in[13];
    const float* be2 = (const float*)d_in[14];
    const float* hw3 = (const float*)d_in[15];
    const float* hb3 = (const float*)d_in[16];
    const float* ga3 = (const float*)d_in[17];
    const float* be3 = (const float*)d_in[18];
    const float* hw4 = (const float*)d_in[19];
    const float* hb4 = (const float*)d_in[20];

    float* out_logits = (float*)d_out;
    float* out_pen    = (float*)d_out + (size_t)NN * 16;
    float* out_feat   = (float*)d_out + (size_t)NN * (16 + 256);

    float *h0, *sums, *cnt, *p1, *p2, *p3, *sc, *sh, *cs, *cq;
    __half *b1p, *b2p, *b3p, *b4p, *b5p;
    int* nz;
    cudaGetSymbolAddress((void**)&h0,   g_h0);
    cudaGetSymbolAddress((void**)&sums, g_sums);
    cudaGetSymbolAddress((void**)&cnt,  g_cnt);
    cudaGetSymbolAddress((void**)&p1,   g_p1);
    cudaGetSymbolAddress((void**)&p2,   g_p2);
    cudaGetSymbolAddress((void**)&p3,   g_p3);
    cudaGetSymbolAddress((void**)&sc,   g_scale);
    cudaGetSymbolAddress((void**)&sh,   g_shift);
    cudaGetSymbolAddress((void**)&cs,   g_cs);
    cudaGetSymbolAddress((void**)&cq,   g_cq);
    cudaGetSymbolAddress((void**)&nz,   g_nz);
    cudaGetSymbolAddress((void**)&b1p, g_b1);
    cudaGetSymbolAddress((void**)&b2p, g_b2);
    cudaGetSymbolAddress((void**)&b3p, g_b3);
    cudaGetSymbolAddress((void**)&b4p, g_b4);
    cudaGetSymbolAddress((void**)&b5p, g_b5);

    const int M = NN;
    const int MT = (M + 127) / 128;   // 782
    dim3 blk(256);
    dim3 gblk(GTH);

    cudaFuncSetAttribute(mgemm<0,1,0>, cudaFuncAttributeMaxDynamicSharedMemorySize, DSM_BYTES);
    cudaFuncSetAttribute(mgemm<2,0,0>, cudaFuncAttributeMaxDynamicSharedMemorySize, DSM_BYTES);
    cudaFuncSetAttribute(mgemm<0,0,1>, cudaFuncAttributeMaxDynamicSharedMemorySize, DSM_BYTES);
    cudaFuncSetAttribute(mgemm<1,0,1>, cudaFuncAttributeMaxDynamicSharedMemorySize, DSM_BYTES);

    // 0: zero everything
    {
        int total = NN * 128 + NN + 1536 * 4;
        zero_all<<<(total / 4 + 255) / 256, blk>>>(sums, cnt, cs, cq, nz);
    }
    // 1: dtype detection
    detect64<<<16, blk>>>((const unsigned int*)ei, nz);
    // 2: all weight packs (fp16)
    tsplit_all<<<(598016 + 255) / 256, blk>>>(w1, wl, wr, hw1, hw2, hw3,
                                              b1p, b2p, b3p, b4p, b5p);
    // 3: G1
    mgemm<0,1,0><<<dim3(1, MT), gblk, DSM_BYTES>>>(x, b1p, b1, h0, M, 64, 128,
        nullptr, nullptr, nullptr, nullptr, nullptr, nullptr);
    // 4: edge scatter
    edge_kernel<<<EE / 64, blk>>>(ei, h0, sums, cnt, nz);
    // 5: G2
    mgemm<2,0,0><<<dim3(1, MT), gblk, DSM_BYTES>>>(sums, b2p, bl, out_feat, M, 256, 128,
        nullptr, nullptr, h0, cnt, nullptr, nullptr);
    // 6: G3 (+stats slice 0)
    mgemm<0,0,1><<<dim3(2, MT), gblk, DSM_BYTES>>>(out_feat, b3p, hb1, p1, M, 128, 256,
        nullptr, nullptr, nullptr, nullptr, cs, cq);
    // 7
    fin_bn<<<1, 256>>>(cs, cq, ga1, be1, sc, sh, 256);
    // 8: G4 (+stats slice 1)
    mgemm<1,0,1><<<dim3(8, MT), gblk, DSM_BYTES>>>(p1, b4p, hb2, p2, M, 256, 1024,
        sc, sh, nullptr, nullptr, cs + 256, cq + 256);
    // 9
    fin_bn<<<4, 256>>>(cs + 256, cq + 256, ga2, be2, sc, sh, 1024);
    // 10: G5 (+stats slice 2)
    mgemm<1,0,1><<<dim3(2, MT), gblk, DSM_BYTES>>>(p2, b5p, hb3, p3, M, 1024, 256,
        sc, sh, nullptr, nullptr, cs + 1280, cq + 1280);
    // 11
    fin_bn<<<1, 256>>>(cs + 1280, cq + 1280, ga3, be3, sc, sh, 256);
    // 12: final
    final_kernel<<<NN / 16, blk>>>(p3, sc, sh, hw4, hb4, out_pen, out_logits);
}

// round 15
// speedup vs baseline: 1.3617x; 1.0656x over previous
#include <cuda_runtime.h>
#include <cuda_fp16.h>
#include <cstdint>

// ---------------- problem constants ----------------
#define NN 100000
#define EE 1600000

// ---------------- scratch (device globals) ----------------
__device__ float  g_h0[(size_t)NN * 128];
__device__ float  g_sums[(size_t)NN * 128];
__device__ float  g_cnt[NN];
__device__ float  g_p1[(size_t)NN * 256];
__device__ float  g_p2[(size_t)NN * 1024];
__device__ float  g_p3[(size_t)NN * 256];
__device__ float  g_cs[1536];      // stats slices: L1 @0(256), L2 @256(1024), L3 @1280(256)
__device__ float  g_cq[1536];
__device__ float  g_scale[1024];
__device__ float  g_shift[1024];
__device__ int    g_nz;            // nonzero high words -> edges are int32
// packed fp16 weights, [N][K] row-major
__device__ __half g_b1[128 * 64];
__device__ __half g_b2[128 * 256];
__device__ __half g_b3[256 * 128];
__device__ __half g_b4[1024 * 256];
__device__ __half g_b5[256 * 1024];

// ---------------- helpers ----------------
__device__ __forceinline__ uint32_t smem_u32(const void* p) {
    uint32_t a;
    asm("{ .reg .u64 t; cvta.to.shared.u64 t, %1; cvt.u32.u64 %0, t; }" : "=r"(a) : "l"(p));
    return a;
}
__device__ __forceinline__ uint32_t h2u(__half2 h) {
    return *reinterpret_cast<uint32_t*>(&h);
}
#define LDSM4(R, addr) \
    asm volatile("ldmatrix.sync.aligned.m8n8.x4.shared.b16 {%0,%1,%2,%3}, [%4];" \
        : "=r"((R)[0]), "=r"((R)[1]), "=r"((R)[2]), "=r"((R)[3]) : "r"(addr))

__device__ __forceinline__ void mma_f16(float* c, const uint32_t* a, const uint32_t* b) {
    asm volatile("mma.sync.aligned.m16n8k16.row.col.f32.f16.f16.f32 "
        "{%0,%1,%2,%3}, {%4,%5,%6,%7}, {%8,%9}, {%0,%1,%2,%3};"
        : "+f"(c[0]), "+f"(c[1]), "+f"(c[2]), "+f"(c[3])
        : "r"(a[0]), "r"(a[1]), "r"(a[2]), "r"(a[3]), "r"(b[0]), "r"(b[1]));
}
#define CP_A16(dst, src) \
    asm volatile("cp.async.ca.shared.global [%0], [%1], 16;" :: "r"(dst), "l"(src))
#define CP_COMMIT()  asm volatile("cp.async.commit_group;")
#define CP_WAIT0()   asm volatile("cp.async.wait_group 0;")
#define CP_WAIT1()   asm volatile("cp.async.wait_group 1;")

// ---------------- prep kernels ----------------
__global__ void zero_all(float* sums, float* cnt, float* cs, float* cq, int* nz) {
    int i = (blockIdx.x * blockDim.x + threadIdx.x) * 4;
    const int n_sums = NN * 128;
    if (i < n_sums) {
        *(float4*)(sums + i) = make_float4(0.f, 0.f, 0.f, 0.f);
    } else {
        int j = i - n_sums;
        if (j < NN) {
            for (int q = 0; q < 4 && j + q < NN; q++) cnt[j + q] = 0.f;
        } else {
            int s = j - NN;
            if (s < 1536) { *(float4*)(cs + s) = make_float4(0.f, 0.f, 0.f, 0.f);
                            *(float4*)(cq + s) = make_float4(0.f, 0.f, 0.f, 0.f); }
            if (s == 0) *nz = 0;
        }
    }
}
__global__ void detect64(const unsigned int* w, int* nz) {
    int t = blockIdx.x * blockDim.x + threadIdx.x;   // [0,4096)
    unsigned int bad = __ballot_sync(0xFFFFFFFFu, w[2 * t + 1] != 0u);
    if ((threadIdx.x & 31) == 0 && bad) atomicOr(nz, 1);
}
// all 5 weight packs, transposed to [N][K] fp16
__global__ void tsplit_all(const float* __restrict__ w1, const float* __restrict__ wl,
                           const float* __restrict__ wr, const float* __restrict__ hw1,
                           const float* __restrict__ hw2, const float* __restrict__ hw3,
                           __half* b1, __half* b2, __half* b3, __half* b4, __half* b5) {
    int idx = blockIdx.x * blockDim.x + threadIdx.x;
    const float* W; __half* bp; int K, N; int local;
    if (idx < 8192)        { local = idx;          W = w1;  bp = b1; K = 64;   N = 128; }
    else if (idx < 40960)  { local = idx - 8192;   W = nullptr; bp = b2; K = 256; N = 128; }
    else if (idx < 73728)  { local = idx - 40960;  W = hw1; bp = b3; K = 128;  N = 256; }
    else if (idx < 335872) { local = idx - 73728;  W = hw2; bp = b4; K = 256;  N = 1024; }
    else if (idx < 598016) { local = idx - 335872; W = hw3; bp = b5; K = 1024; N = 256; }
    else return;
    int n = local / K, k = local % K;
    float v;
    if (W) v = W[(size_t)k * N + n];
    else   v = (k < 128) ? wl[k * 128 + n] : wr[(k - 128) * 128 + n];
    bp[(size_t)n * K + k] = __float2half_rn(v);
}

// ---------------- edge scatter (8 edges per warp) ----------------
__global__ void edge_kernel(const void* __restrict__ ei, const float* __restrict__ h0,
                            float* __restrict__ sums, float* __restrict__ cnt,
                            const int* __restrict__ nz) {
    int warp0 = ((blockIdx.x * blockDim.x + threadIdx.x) >> 5) * 8;
    int lane = threadIdx.x & 31;
    const int is64 = (*nz == 0);
#pragma unroll
    for (int e = warp0; e < warp0 + 8; e++) {
        long long src, dst;
        if (is64) {
            const long long* p = (const long long*)ei;
            src = p[e]; dst = p[EE + e];
        } else {
            const int* p = (const int*)ei;
            src = p[e]; dst = p[EE + e];
        }
        float4 v = *(const float4*)(h0 + src * 128 + lane * 4);
        float* d = sums + dst * 128 + lane * 4;
        asm volatile("red.global.add.v4.f32 [%0], {%1, %2, %3, %4};"
                     :: "l"(d), "f"(v.x), "f"(v.y), "f"(v.z), "f"(v.w) : "memory");
        if (lane == 0) atomicAdd(cnt + dst, 1.0f);
    }
}

__global__ void fin_bn(const float* __restrict__ cs, const float* __restrict__ cq,
                       const float* __restrict__ gm, const float* __restrict__ bt,
                       float* __restrict__ sc, float* __restrict__ sh, int ncols) {
    int c = blockIdx.x * blockDim.x + threadIdx.x;
    if (c < ncols) {
        double mean = (double)cs[c] * (1.0 / (double)NN);
        double var  = (double)cq[c] * (1.0 / (double)NN) - mean * mean;
        if (var < 0.0) var = 0.0;
        float rstd = (float)(1.0 / sqrt(var + 1e-5));
        float s = gm[c] * rstd;
        sc[c] = s;
        sh[c] = bt[c] - (float)mean * s;
    }
}

// ---------------- pipelined mma.sync fp16x2 GEMM (BK=64, 512 threads) -------
// C[M,N] = T(A)[M,K] @ W + bias.  A split fp16 hi/lo; B single fp16 [N][K].
// MODE 0: plain | MODE 1: relu(a*sc+sh) | MODE 2: k<128: A(sums)/cnt; else aux(h0)
// CTA tile 128x128, BK=64, 16 warps (warp tile 32M x 32N). 1 barrier per chunk.
// smem: sA 2 x (128 rows x 256B) = 64KB;  sB 2 x (128 rows x 128B) = 32KB
#define DSM_BYTES 98304
#define GTH 512

template<int MODE, int RELU, int STATS>
__global__ void __launch_bounds__(GTH, 1)
mgemm(const float* __restrict__ A, const __half* __restrict__ Bpk,
      const float* __restrict__ bias, float* __restrict__ C,
      int M, int K, int N,
      const float* __restrict__ sc, const float* __restrict__ sh,
      const float* __restrict__ aux, const float* __restrict__ cnt,
      float* __restrict__ gs, float* __restrict__ gq) {
    extern __shared__ __align__(16) char dsm[];
    char* sAc = dsm;
    const uint32_t sA_b = smem_u32(dsm);
    const uint32_t sB_b = sA_b + 65536;

    const int tid = threadIdx.x, lane = tid & 31, wid = tid >> 5;
    const int wm = (wid & 3) * 32, wn = (wid >> 2) * 32;
    const int m0 = blockIdx.y * 128, n0 = blockIdx.x * 128;
    const int nch = K >> 6;

    float acc[2][4][4];
#pragma unroll
    for (int i = 0; i < 2; i++)
#pragma unroll
        for (int j = 0; j < 4; j++)
#pragma unroll
            for (int q = 0; q < 4; q++) acc[i][j][q] = 0.f;

    // ---- B chunk c: 128 rows x 64 fp16 = 128B/row, swizzled ----
    auto issueB = [&](int c) {
        const int buf = c & 1;
        const uint32_t bb = sB_b + buf * 16384;
#pragma unroll
        for (int l = 0; l < 2; l++) {
            int pos = tid + l * GTH;
            int row = pos >> 3, q = pos & 7;
            const char* srcB = (const char*)(Bpk + (size_t)(n0 + row) * K + c * 64) + q * 16;
            uint32_t dst = bb + row * 128 + (((uint32_t)(q * 16)) ^ (uint32_t)((row & 7) * 16));
            CP_A16(dst, srcB);
        }
        CP_COMMIT();
    };

    auto load_A = [&](int c, float4* rv) {
        const int k0 = c << 6;
#pragma unroll
        for (int l = 0; l < 4; l++) {
            int pos = tid + l * GTH;
            int row = pos >> 4, q = pos & 15;
            int grow = m0 + row;
            float4 v = make_float4(0.f, 0.f, 0.f, 0.f);
            if (grow < M) {
                if (MODE == 2) {
                    if (k0 < 128) v = *(const float4*)(A + (size_t)grow * 128 + k0 + q * 4);
                    else          v = *(const float4*)(aux + (size_t)grow * 128 + (k0 - 128) + q * 4);
                } else {
                    v = *(const float4*)(A + (size_t)grow * K + k0 + q * 4);
                }
            }
            rv[l] = v;
        }
    };
    // A row 256B: group (q>>3)*128; hi at +0..63, lo at +64..127; in-group byte (q&7)*8
    auto split_store = [&](int c, float4* rv) {
        const int buf = c & 1;
        const int k0 = c << 6;
        char* sAd = sAc + buf * 32768;
#pragma unroll
        for (int l = 0; l < 4; l++) {
            int pos = tid + l * GTH;
            int row = pos >> 4, q = pos & 15;
            int grow = m0 + row;
            float4 v = rv[l];
            if (MODE == 1) {
                float4 s4 = *(const float4*)(sc + k0 + q * 4);
                float4 h4 = *(const float4*)(sh + k0 + q * 4);
                v.x = fmaxf(fmaf(v.x, s4.x, h4.x), 0.f);
                v.y = fmaxf(fmaf(v.y, s4.y, h4.y), 0.f);
                v.z = fmaxf(fmaf(v.z, s4.z, h4.z), 0.f);
                v.w = fmaxf(fmaf(v.w, s4.w, h4.w), 0.f);
            }
            if (MODE == 2 && k0 < 128) {
                float cv = (grow < M) ? cnt[grow] : 1.f;
                float ic = 1.f / fmaxf(cv, 1.f);
                v.x *= ic; v.y *= ic; v.z *= ic; v.w *= ic;
            }
            // packed fp16 split: hi = rn(v), lo = rn(v - hi)
            __half2 h2a = __float22half2_rn(make_float2(v.x, v.y));
            float2  f2a = __half22float2(h2a);
            __half2 l2a = __float22half2_rn(make_float2(v.x - f2a.x, v.y - f2a.y));
            __half2 h2b = __float22half2_rn(make_float2(v.z, v.w));
            float2  f2b = __half22float2(h2b);
            __half2 l2b = __float22half2_rn(make_float2(v.z - f2b.x, v.w - f2b.y));
            uint2 hi2 = make_uint2(h2u(h2a), h2u(h2b));
            uint2 lo2 = make_uint2(h2u(l2a), h2u(l2b));
            uint32_t xr = (uint32_t)((row & 7) * 16);
            uint32_t base = (uint32_t)(row * 256 + (q >> 3) * 128);
            uint32_t qq = (uint32_t)((q & 7) * 8);
            *(uint2*)(sAd + base + (qq ^ xr)) = hi2;
            *(uint2*)(sAd + base + ((64 + qq) ^ xr)) = lo2;
        }
    };

    // ---- prologue ----
    issueB(0);
    if (nch > 1) issueB(1);
    {
        float4 rv0[4];
        load_A(0, rv0);
        split_store(0, rv0);
    }
    if (nch > 1) CP_WAIT1(); else CP_WAIT0();
    __syncthreads();

    // ---- mainloop: one barrier per 64-k chunk ----
    for (int c = 0; c < nch; c++) {
        const int buf = c & 1;
        float4 rv[4];
        if (c + 1 < nch) load_A(c + 1, rv);
        const uint32_t ab = sA_b + buf * 32768;
        const uint32_t bb = sB_b + buf * 16384;
#pragma unroll
        for (int ks = 0; ks < 4; ks++) {
            const uint32_t gb = (uint32_t)((ks >> 1) * 128);
            const uint32_t kb = (uint32_t)((ks & 1) * 32);
            uint32_t afh[2][4], afl[2][4];
#pragma unroll
            for (int mt = 0; mt < 2; mt++) {
                int row = wm + mt * 16 + (lane & 15);
                uint32_t cb = kb + (uint32_t)((lane >> 4) * 16);
                uint32_t x = (uint32_t)((row & 7) * 16);
                uint32_t rb = ab + row * 256 + gb;
                LDSM4(afh[mt], rb + (cb ^ x));
                LDSM4(afl[mt], rb + ((cb + 64) ^ x));
            }
            uint32_t bf[2][4];
#pragma unroll
            for (int np = 0; np < 2; np++) {
                int row = wn + np * 16 + (lane & 7) + ((lane >> 4) & 1) * 8;
                uint32_t cb = (uint32_t)(ks * 32) + (uint32_t)(((lane >> 3) & 1) * 16);
                uint32_t x = (uint32_t)((row & 7) * 16);
                LDSM4(bf[np], bb + row * 128 + (cb ^ x));
            }
#pragma unroll
            for (int mt = 0; mt < 2; mt++)
#pragma unroll
                for (int np = 0; np < 2; np++)
#pragma unroll
                    for (int sub = 0; sub < 2; sub++) {
                        int nt = np * 2 + sub;
                        mma_f16(acc[mt][nt], afh[mt], &bf[np][sub * 2]);
                        mma_f16(acc[mt][nt], afl[mt], &bf[np][sub * 2]);
                    }
        }
        if (c + 1 < nch) {
            split_store(c + 1, rv);
            CP_WAIT0();
        }
        __syncthreads();
        if (c + 2 < nch) issueB(c + 2);
    }

    // ---- epilogue ----
    float* ssum = (float*)dsm;
    if (STATS) {
        if (tid < 256) ssum[tid] = 0.f;
        __syncthreads();
    }
#pragma unroll
    for (int mt = 0; mt < 2; mt++) {
        int row = m0 + wm + mt * 16 + (lane >> 2);
#pragma unroll
        for (int nt = 0; nt < 4; nt++) {
            int col = n0 + wn + nt * 8 + (lane & 3) * 2;
            float b0 = bias[col], b1 = bias[col + 1];
            float2 o0 = make_float2(acc[mt][nt][0] + b0, acc[mt][nt][1] + b1);
            float2 o1 = make_float2(acc[mt][nt][2] + b0, acc[mt][nt][3] + b1);
            if (RELU) {
                o0.x = fmaxf(o0.x, 0.f); o0.y = fmaxf(o0.y, 0.f);
                o1.x = fmaxf(o1.x, 0.f); o1.y = fmaxf(o1.y, 0.f);
            }
            if (row < M)     *(float2*)(C + (size_t)row * N + col) = o0;
            if (row + 8 < M) *(float2*)(C + (size_t)(row + 8) * N + col) = o1;
        }
    }
    if (STATS) {
#pragma unroll
        for (int nt = 0; nt < 4; nt++) {
            int colr = wn + nt * 8 + (lane & 3) * 2;
            float b0 = bias[n0 + colr], b1 = bias[n0 + colr + 1];
            float s0 = 0.f, s1 = 0.f, q0 = 0.f, q1 = 0.f;
#pragma unroll
            for (int mt = 0; mt < 2; mt++) {
                int r = m0 + wm + mt * 16 + (lane >> 2);
                float ok0 = (r < M) ? 1.f : 0.f;
                float ok1 = (r + 8 < M) ? 1.f : 0.f;
                float v00 = (acc[mt][nt][0] + b0) * ok0;
                float v01 = (acc[mt][nt][1] + b1) * ok0;
                float v10 = (acc[mt][nt][2] + b0) * ok1;
                float v11 = (acc[mt][nt][3] + b1) * ok1;
                s0 += v00 + v10; s1 += v01 + v11;
                q0 += v00 * v00 + v10 * v10;
                q1 += v01 * v01 + v11 * v11;
            }
#pragma unroll
            for (int d = 4; d < 32; d <<= 1) {
                s0 += __shfl_xor_sync(0xFFFFFFFFu, s0, d);
                s1 += __shfl_xor_sync(0xFFFFFFFFu, s1, d);
                q0 += __shfl_xor_sync(0xFFFFFFFFu, q0, d);
                q1 += __shfl_xor_sync(0xFFFFFFFFu, q1, d);
            }
            if (lane < 4) {
                atomicAdd(&ssum[colr], s0);
                atomicAdd(&ssum[colr + 1], s1);
                atomicAdd(&ssum[128 + colr], q0);
                atomicAdd(&ssum[128 + colr + 1], q1);
            }
        }
        __syncthreads();
        if (tid < 128)       atomicAdd(&gs[n0 + tid], ssum[tid]);
        else if (tid < 256)  atomicAdd(&gq[n0 + tid - 128], ssum[tid]);
    }
}

// ---------------- final layer (float4 streaming) ----------------
__global__ __launch_bounds__(256)
void final_kernel(const float* __restrict__ g3,
                  const float* __restrict__ sc, const float* __restrict__ sh,
                  const float* __restrict__ hw4, const float* __restrict__ hb4,
                  float* __restrict__ pen, float* __restrict__ logits) {
    __shared__ float w4s[256 * 16];
    __shared__ float at[16 * 256];
    int t = threadIdx.x;
    for (int i = t; i < 4096; i += 256) w4s[i] = hw4[i];
    long long r0 = (long long)blockIdx.x * 16;
    // 16 rows, 4 per iteration; thread t: row = it*4 + (t>>6), cols (t&63)*4..+3
    {
        int col = (t & 63) * 4;
        float4 s4 = *(const float4*)(sc + col);
        float4 h4 = *(const float4*)(sh + col);
#pragma unroll
        for (int it = 0; it < 4; it++) {
            int row = it * 4 + (t >> 6);
            float4 v = *(const float4*)(g3 + (r0 + row) * 256 + col);
            v.x = fmaxf(fmaf(v.x, s4.x, h4.x), 0.f);
            v.y = fmaxf(fmaf(v.y, s4.y, h4.y), 0.f);
            v.z = fmaxf(fmaf(v.z, s4.z, h4.z), 0.f);
            v.w = fmaxf(fmaf(v.w, s4.w, h4.w), 0.f);
            *(float4*)(&at[row * 256 + col]) = v;
            *(float4*)(pen + (r0 + row) * 256 + col) = v;
        }
    }
    __syncthreads();
    int r = t >> 4, c = t & 15;
    float acc = hb4[c];
#pragma unroll 8
    for (int k = 0; k < 256; k++)
        acc = fmaf(at[r * 256 + k], w4s[k * 16 + c], acc);
    logits[(r0 + r) * 16 + c] = acc;
}

// ---------------- launch ----------------
extern "C" void kernel_launch(void* const* d_in, const int* in_sizes, int n_in,
                              void* d_out, int out_size) {
    const float* x   = (const float*)d_in[0];
    const void*  ei  = d_in[1];
    const float* w1  = (const float*)d_in[2];
    const float* b1  = (const float*)d_in[3];
    const float* wl  = (const float*)d_in[4];
    const float* bl  = (const float*)d_in[5];
    const float* wr  = (const float*)d_in[6];
    const float* hw1 = (const float*)d_in[7];
    const float* hb1 = (const float*)d_in[8];
    const float* ga1 = (const float*)d_in[9];
    const float* be1 = (const float*)d_in[10];
    const float* hw2 = (const float*)d_in[11];
    const float* hb2 = (const float*)d_in[12];
    const float* ga2 = (const float*)d_in[13];
    const float* be2 = (const float*)d_in[14];
    const float* hw3 = (const float*)d_in[15];
    const float* hb3 = (const float*)d_in[16];
    const float* ga3 = (const float*)d_in[17];
    const float* be3 = (const float*)d_in[18];
    const float* hw4 = (const float*)d_in[19];
    const float* hb4 = (const float*)d_in[20];

    float* out_logits = (float*)d_out;
    float* out_pen    = (float*)d_out + (size_t)NN * 16;
    float* out_feat   = (float*)d_out + (size_t)NN * (16 + 256);

    float *h0, *sums, *cnt, *p1, *p2, *p3, *sc, *sh, *cs, *cq;
    __half *b1p, *b2p, *b3p, *b4p, *b5p;
    int* nz;
    cudaGetSymbolAddress((void**)&h0,   g_h0);
    cudaGetSymbolAddress((void**)&sums, g_sums);
    cudaGetSymbolAddress((void**)&cnt,  g_cnt);
    cudaGetSymbolAddress((void**)&p1,   g_p1);
    cudaGetSymbolAddress((void**)&p2,   g_p2);
    cudaGetSymbolAddress((void**)&p3,   g_p3);
    cudaGetSymbolAddress((void**)&sc,   g_scale);
    cudaGetSymbolAddress((void**)&sh,   g_shift);
    cudaGetSymbolAddress((void**)&cs,   g_cs);
    cudaGetSymbolAddress((void**)&cq,   g_cq);
    cudaGetSymbolAddress((void**)&nz,   g_nz);
    cudaGetSymbolAddress((void**)&b1p, g_b1);
    cudaGetSymbolAddress((void**)&b2p, g_b2);
    cudaGetSymbolAddress((void**)&b3p, g_b3);
    cudaGetSymbolAddress((void**)&b4p, g_b4);
    cudaGetSymbolAddress((void**)&b5p, g_b5);

    const int M = NN;
    const int MT = (M + 127) / 128;   // 782
    dim3 blk(256);
    dim3 gblk(GTH);

    cudaFuncSetAttribute(mgemm<0,1,0>, cudaFuncAttributeMaxDynamicSharedMemorySize, DSM_BYTES);
    cudaFuncSetAttribute(mgemm<2,0,0>, cudaFuncAttributeMaxDynamicSharedMemorySize, DSM_BYTES);
    cudaFuncSetAttribute(mgemm<0,0,1>, cudaFuncAttributeMaxDynamicSharedMemorySize, DSM_BYTES);
    cudaFuncSetAttribute(mgemm<1,0,1>, cudaFuncAttributeMaxDynamicSharedMemorySize, DSM_BYTES);

    // 0: zero everything
    {
        int total = NN * 128 + NN + 1536 * 4;
        zero_all<<<(total / 4 + 255) / 256, blk>>>(sums, cnt, cs, cq, nz);
    }
    // 1: dtype detection
    detect64<<<16, blk>>>((const unsigned int*)ei, nz);
    // 2: all weight packs (fp16)
    tsplit_all<<<(598016 + 255) / 256, blk>>>(w1, wl, wr, hw1, hw2, hw3,
                                              b1p, b2p, b3p, b4p, b5p);
    // 3: G1
    mgemm<0,1,0><<<dim3(1, MT), gblk, DSM_BYTES>>>(x, b1p, b1, h0, M, 64, 128,
        nullptr, nullptr, nullptr, nullptr, nullptr, nullptr);
    // 4: edge scatter
    edge_kernel<<<EE / 64, blk>>>(ei, h0, sums, cnt, nz);
    // 5: G2
    mgemm<2,0,0><<<dim3(1, MT), gblk, DSM_BYTES>>>(sums, b2p, bl, out_feat, M, 256, 128,
        nullptr, nullptr, h0, cnt, nullptr, nullptr);
    // 6: G3 (+stats slice 0)
    mgemm<0,0,1><<<dim3(2, MT), gblk, DSM_BYTES>>>(out_feat, b3p, hb1, p1, M, 128, 256,
        nullptr, nullptr, nullptr, nullptr, cs, cq);
    // 7
    fin_bn<<<1, 256>>>(cs, cq, ga1, be1, sc, sh, 256);
    // 8: G4 (+stats slice 1)
    mgemm<1,0,1><<<dim3(8, MT), gblk, DSM_BYTES>>>(p1, b4p, hb2, p2, M, 256, 1024,
        sc, sh, nullptr, nullptr, cs + 256, cq + 256);
    // 9
    fin_bn<<<4, 256>>>(cs + 256, cq + 256, ga2, be2, sc, sh, 1024);
    // 10: G5 (+stats slice 2)
    mgemm<1,0,1><<<dim3(2, MT), gblk, DSM_BYTES>>>(p2, b5p, hb3, p3, M, 1024, 256,
        sc, sh, nullptr, nullptr, cs + 1280, cq + 1280);
    // 11
    fin_bn<<<1, 256>>>(cs + 1280, cq + 1280, ga3, be3, sc, sh, 256);
    // 12: final
    final_kernel<<<NN / 16, blk>>>(p3, sc, sh, hw4, hb4, out_pen, out_logits);
}